// round 2
// baseline (speedup 1.0000x reference)
#include <cuda_runtime.h>

// Problem constants
#define SS 8        // streams
#define II 64       // modulations per stream
#define MM 256      // features per stream
#define NTOK 16384  // batch
#define TT 128      // tokens per CTA in main kernel

// Fused weights: W~_g[s] = Wg[:, :, 0:M] @ Wx[s]  -> [4][S][M][I]
__device__ float g_wfused[4][SS][MM][II];
// Fused biases:  b~_g[s,m] = bg + Wg_x@bx + Wg_h@h0
__device__ float g_bfused[4][SS][MM];

// ---------------------------------------------------------------------------
// helpers
// ---------------------------------------------------------------------------
__device__ __forceinline__ void ffma2(unsigned long long& d,
                                      unsigned long long a,
                                      unsigned long long b) {
    asm("fma.rn.f32x2 %0, %1, %2, %0;" : "+l"(d) : "l"(a), "l"(b));
}

__device__ __forceinline__ float2 unpack2(unsigned long long v) {
    float2 r;
    asm("mov.b64 {%0, %1}, %2;" : "=f"(r.x), "=f"(r.y) : "l"(v));
    return r;
}

__device__ __forceinline__ float sigmoid_f(float x) {
    float e = __expf(-x);              // MUFU.EX2 + mul
    return __fdividef(1.0f, 1.0f + e); // MUFU.RCP + mul
}

__device__ __forceinline__ float tanh_f(float x) {
    float e = __expf(-2.0f * x);
    return __fdividef(2.0f, 1.0f + e) - 1.0f;
}

// ---------------------------------------------------------------------------
// Kernel 1: weight/bias fusion
// grid = (S, 4 gates, 4 m-blocks of 64), block = 256
// smem: wx_s[256*64] (Wx[s], 64KB) + wg_s[64*256] (x-half of gate rows, 64KB)
// ---------------------------------------------------------------------------
__global__ __launch_bounds__(256, 1)
void precompute_kernel(const float* __restrict__ Wx, const float* __restrict__ bx,
                       const float* __restrict__ Wi, const float* __restrict__ bi,
                       const float* __restrict__ Wf, const float* __restrict__ bf,
                       const float* __restrict__ Wg, const float* __restrict__ bg,
                       const float* __restrict__ Wo, const float* __restrict__ bo,
                       const float* __restrict__ h0) {
    extern __shared__ float smem[];
    float* wx_s = smem;            // [k=256][i=64]
    float* wg_s = smem + 256 * 64; // [mm=64][k=256]

    const int s    = blockIdx.x;
    const int gate = blockIdx.y;
    const int m0   = blockIdx.z * 64;
    const int tid  = threadIdx.x;

    const float* WG;
    const float* bG;
    switch (gate) {
        case 0:  WG = Wi; bG = bi; break;
        case 1:  WG = Wf; bG = bf; break;
        case 2:  WG = Wg; bG = bg; break;
        default: WG = Wo; bG = bo; break;
    }

    // stage Wx[s] (layout [k][i] == linear) and the 64 gate rows (x-half only)
    for (int idx = tid; idx < 256 * 64; idx += 256)
        wx_s[idx] = Wx[(size_t)s * 256 * 64 + idx];
    for (int idx = tid; idx < 64 * 256; idx += 256) {
        int mm = idx >> 8, k = idx & 255;
        wg_s[idx] = WG[(size_t)(s * 256 + m0 + mm) * 512 + k];
    }
    __syncthreads();

    const int tx = tid & 63;  // i column
    const int ty = tid >> 6;  // 0..3 (fixed per warp: 64 tx per ty)

    float acc[16];
#pragma unroll
    for (int r = 0; r < 16; r++) acc[r] = 0.0f;

    for (int k = 0; k < 256; k += 4) {
        float x0 = wx_s[(k + 0) * 64 + tx];
        float x1 = wx_s[(k + 1) * 64 + tx];
        float x2 = wx_s[(k + 2) * 64 + tx];
        float x3 = wx_s[(k + 3) * 64 + tx];
#pragma unroll
        for (int r = 0; r < 16; r++) {
            int ml = ty + 4 * r;
            float4 wv = *reinterpret_cast<const float4*>(&wg_s[ml * 256 + k]);
            acc[r] += wv.x * x0;
            acc[r] += wv.y * x1;
            acc[r] += wv.z * x2;
            acc[r] += wv.w * x3;
        }
    }
#pragma unroll
    for (int r = 0; r < 16; r++)
        g_wfused[gate][s][m0 + ty + 4 * r][tx] = acc[r];

    // fused bias for this block's 64 rows
    if (tid < 64) {
        int m = m0 + tid;
        const float* row = WG + (size_t)(s * 256 + m) * 512;
        float accb = bG[s * 256 + m];
        for (int k = 0; k < 256; k++) accb += row[k] * bx[s * 256 + k];
        for (int k = 0; k < 256; k++) accb += row[256 + k] * h0[s * 256 + k];
        g_bfused[gate][s][m] = accb;
    }
}

// ---------------------------------------------------------------------------
// Kernel 2: main LSTM step
// grid = (N/TT, 2 m-halves, S), block = 256 threads = (gate[4] x m2[64])
// Each thread owns 2 output rows (m, m+1): 2x32 packed f32x2 weights in regs.
// smem: xs[TT*64] (32KB token slab) + act[8][4][128] (16KB) = 48KB
// ---------------------------------------------------------------------------
__global__ __launch_bounds__(256, 1)
void lstm_main_kernel(const float* __restrict__ mod,
                      const float* __restrict__ c0,
                      float* __restrict__ out) {
    extern __shared__ float smem[];
    float* xs  = smem;            // [TT][64]
    float* act = smem + TT * 64;  // [8][4][128]

    const int s   = blockIdx.z;
    const int mh  = blockIdx.y;
    const int n0  = blockIdx.x * TT;
    const int tid = threadIdx.x;
    const int g   = tid >> 6;   // gate 0=i,1=f,2=g,3=o
    const int m2  = tid & 63;
    const int m   = mh * 128 + m2 * 2;

    // loop-invariant packed weights in registers
    unsigned long long w0[32], w1[32];
    {
        const unsigned long long* wp0 =
            reinterpret_cast<const unsigned long long*>(g_wfused[g][s][m]);
        const unsigned long long* wp1 =
            reinterpret_cast<const unsigned long long*>(g_wfused[g][s][m + 1]);
#pragma unroll
        for (int j = 0; j < 32; j++) { w0[j] = wp0[j]; w1[j] = wp1[j]; }
    }
    const float bias0 = g_bfused[g][s][m];
    const float bias1 = g_bfused[g][s][m + 1];

    // stage this CTA's token slab: mod[n][s*64 .. s*64+63]
    for (int idx = tid; idx < TT * 16; idx += 256) {
        int tt = idx >> 4, q = idx & 15;
        float4 v = reinterpret_cast<const float4*>(
                       mod + (size_t)(n0 + tt) * (SS * II) + s * II)[q];
        reinterpret_cast<float4*>(xs + tt * 64)[q] = v;
    }
    __syncthreads();

    for (int t8 = 0; t8 < TT; t8 += 8) {
        for (int tt = 0; tt < 8; tt++) {
            const int t = t8 + tt;
            const unsigned long long* xp =
                reinterpret_cast<const unsigned long long*>(xs + t * 64);

            unsigned long long a0 = 0, a1 = 0, a2 = 0, a3 = 0;
            unsigned long long b0 = 0, b1 = 0, b2 = 0, b3 = 0;
#pragma unroll
            for (int j = 0; j < 32; j += 4) {
                unsigned long long xv0 = xp[j + 0];
                unsigned long long xv1 = xp[j + 1];
                unsigned long long xv2 = xp[j + 2];
                unsigned long long xv3 = xp[j + 3];
                ffma2(a0, w0[j + 0], xv0); ffma2(b0, w1[j + 0], xv0);
                ffma2(a1, w0[j + 1], xv1); ffma2(b1, w1[j + 1], xv1);
                ffma2(a2, w0[j + 2], xv2); ffma2(b2, w1[j + 2], xv2);
                ffma2(a3, w0[j + 3], xv3); ffma2(b3, w1[j + 3], xv3);
            }
            float2 fa0 = unpack2(a0), fa1 = unpack2(a1);
            float2 fa2 = unpack2(a2), fa3 = unpack2(a3);
            float2 fb0 = unpack2(b0), fb1 = unpack2(b1);
            float2 fb2 = unpack2(b2), fb3 = unpack2(b3);
            float pre0 = bias0 + ((fa0.x + fa0.y) + (fa1.x + fa1.y)) +
                                 ((fa2.x + fa2.y) + (fa3.x + fa3.y));
            float pre1 = bias1 + ((fb0.x + fb0.y) + (fb1.x + fb1.y)) +
                                 ((fb2.x + fb2.y) + (fb3.x + fb3.y));

            float v0, v1;
            if (g == 2) { v0 = tanh_f(pre0);    v1 = tanh_f(pre1); }
            else        { v0 = sigmoid_f(pre0); v1 = sigmoid_f(pre1); }
            reinterpret_cast<float2*>(act + (tt * 4 + g) * 128)[m2] =
                make_float2(v0, v1);
        }
        __syncthreads();

#pragma unroll
        for (int rep = 0; rep < 4; rep++) {
            int idx = rep * 256 + tid;
            int tt = idx >> 7, mm = idx & 127;
            float iv = act[(tt * 4 + 0) * 128 + mm];
            float fv = act[(tt * 4 + 1) * 128 + mm];
            float gv = act[(tt * 4 + 2) * 128 + mm];
            float ov = act[(tt * 4 + 3) * 128 + mm];
            float c0v = c0[s * 256 + mh * 128 + mm];
            float cc = fv * c0v + iv * gv;
            float hh = ov * tanh_f(cc);
            out[(size_t)(n0 + t8 + tt) * (SS * MM) + s * 256 + mh * 128 + mm] = hh;
        }
        __syncthreads();
    }
}

// ---------------------------------------------------------------------------
// launch
// ---------------------------------------------------------------------------
extern "C" void kernel_launch(void* const* d_in, const int* in_sizes, int n_in,
                              void* d_out, int out_size) {
    const float* mod = (const float*)d_in[0];
    const float* h0  = (const float*)d_in[1];
    const float* c0  = (const float*)d_in[2];
    const float* Wx  = (const float*)d_in[3];
    const float* bx  = (const float*)d_in[4];
    const float* Wi  = (const float*)d_in[5];
    const float* bi  = (const float*)d_in[6];
    const float* Wf  = (const float*)d_in[7];
    const float* bf  = (const float*)d_in[8];
    const float* Wg  = (const float*)d_in[9];
    const float* bg  = (const float*)d_in[10];
    const float* Wo  = (const float*)d_in[11];
    const float* bo  = (const float*)d_in[12];
    float* out = (float*)d_out;

    cudaFuncSetAttribute(precompute_kernel,
                         cudaFuncAttributeMaxDynamicSharedMemorySize, 131072);
    cudaFuncSetAttribute(lstm_main_kernel,
                         cudaFuncAttributeMaxDynamicSharedMemorySize, 49152);

    precompute_kernel<<<dim3(SS, 4, 4), 256, 131072>>>(
        Wx, bx, Wi, bi, Wf, bf, Wg, bg, Wo, bo, h0);

    lstm_main_kernel<<<dim3(NTOK / TT, 2, SS), 256, (TT * 64 + 8 * 4 * 128) * 4>>>(
        mod, c0, out);
}

// round 4
// speedup vs baseline: 2.8778x; 2.8778x over previous
#include <cuda_runtime.h>
#include <cuda_bf16.h>
#include <cstdint>

// Problem constants
#define SS 8        // streams
#define II 64       // modulations per stream
#define MM 256      // features per stream
#define NTOK 16384  // batch

// Fused weights (bf16 hi/lo split): W~_g[s] = Wg[:, :, 0:M] @ Wx[s]  -> [4][S][M][64]
__device__ __nv_bfloat16 g_wbh[4][SS][MM][II];
__device__ __nv_bfloat16 g_wbl[4][SS][MM][II];
// Fused biases:  b~_g[s,m] = bg + Wg_x@bx + Wg_h@h0
__device__ float g_bias[4][SS][MM];

// ---------------------------------------------------------------------------
// helpers
// ---------------------------------------------------------------------------
__device__ __forceinline__ float sigmoid_f(float x) {
    float e = __expf(-x);
    return __fdividef(1.0f, 1.0f + e);
}
__device__ __forceinline__ float tanh_f(float x) {
    float e = __expf(-2.0f * x);
    return __fdividef(2.0f, 1.0f + e) - 1.0f;
}

// pack two floats into bf16x2: low half = lo, high half = hi
__device__ __forceinline__ uint32_t pack_bf16x2(float lo, float hi) {
    uint32_t r;
    asm("cvt.rn.bf16x2.f32 %0, %1, %2;" : "=r"(r) : "f"(hi), "f"(lo));
    return r;
}

__device__ __forceinline__ uint32_t smem_u32(const void* p) {
    uint32_t a;
    asm("{ .reg .u64 t; cvta.to.shared.u64 t, %1; cvt.u32.u64 %0, t; }"
        : "=r"(a) : "l"(p));
    return a;
}

__device__ __forceinline__ void ldsm4(uint32_t& r0, uint32_t& r1,
                                      uint32_t& r2, uint32_t& r3, uint32_t addr) {
    asm volatile("ldmatrix.sync.aligned.m8n8.x4.shared.b16 {%0,%1,%2,%3}, [%4];"
                 : "=r"(r0), "=r"(r1), "=r"(r2), "=r"(r3) : "r"(addr));
}

__device__ __forceinline__ void mma16816(float* c, const uint32_t* a,
                                         uint32_t b0, uint32_t b1) {
    asm volatile(
        "mma.sync.aligned.m16n8k16.row.col.f32.bf16.bf16.f32 "
        "{%0,%1,%2,%3}, {%4,%5,%6,%7}, {%8,%9}, {%0,%1,%2,%3};"
        : "+f"(c[0]), "+f"(c[1]), "+f"(c[2]), "+f"(c[3])
        : "r"(a[0]), "r"(a[1]), "r"(a[2]), "r"(a[3]), "r"(b0), "r"(b1));
}

// swizzled smem byte offset for rows of 128B: XOR 16B-chunk by (row&7)
__device__ __forceinline__ uint32_t swz(uint32_t row, uint32_t colbyte) {
    return row * 128u + (colbyte ^ ((row & 7u) << 4));
}

// ---------------------------------------------------------------------------
// Kernel 1: weight/bias fusion
// grid = (S, 4 gates, 4 m-blocks of 64), block = 256
// smem: wx_s[256*64] (Wx[s], 64KB) + wg_s[64*256] (x-half of gate rows, 64KB)
// ---------------------------------------------------------------------------
__global__ __launch_bounds__(256, 1)
void precompute_kernel(const float* __restrict__ Wx, const float* __restrict__ bx,
                       const float* __restrict__ Wi, const float* __restrict__ bi,
                       const float* __restrict__ Wf, const float* __restrict__ bf,
                       const float* __restrict__ Wg, const float* __restrict__ bg,
                       const float* __restrict__ Wo, const float* __restrict__ bo,
                       const float* __restrict__ h0) {
    extern __shared__ float smem[];
    float* wx_s = smem;            // [k=256][i=64]
    float* wg_s = smem + 256 * 64; // [mm=64][k=256]

    const int s    = blockIdx.x;
    const int gate = blockIdx.y;
    const int m0   = blockIdx.z * 64;
    const int tid  = threadIdx.x;

    const float* WG;
    const float* bG;
    switch (gate) {
        case 0:  WG = Wi; bG = bi; break;
        case 1:  WG = Wf; bG = bf; break;
        case 2:  WG = Wg; bG = bg; break;
        default: WG = Wo; bG = bo; break;
    }

    for (int idx = tid; idx < 256 * 64; idx += 256) {
        wx_s[idx] = Wx[(size_t)s * 256 * 64 + idx];
    }
    for (int idx = tid; idx < 64 * 256; idx += 256) {
        int mm = idx >> 8, k = idx & 255;
        wg_s[idx] = WG[(size_t)(s * 256 + m0 + mm) * 512 + k];
    }
    __syncthreads();

    const int tx = tid & 63;  // i column
    const int ty = tid >> 6;  // 0..3

    float acc[16];
#pragma unroll
    for (int r = 0; r < 16; r++) {
        acc[r] = 0.0f;
    }

    for (int k = 0; k < 256; k += 4) {
        float x0 = wx_s[(k + 0) * 64 + tx];
        float x1 = wx_s[(k + 1) * 64 + tx];
        float x2 = wx_s[(k + 2) * 64 + tx];
        float x3 = wx_s[(k + 3) * 64 + tx];
#pragma unroll
        for (int r = 0; r < 16; r++) {
            int ml = ty + 4 * r;
            float4 wv = *reinterpret_cast<const float4*>(&wg_s[ml * 256 + k]);
            acc[r] += wv.x * x0;
            acc[r] += wv.y * x1;
            acc[r] += wv.z * x2;
            acc[r] += wv.w * x3;
        }
    }
#pragma unroll
    for (int r = 0; r < 16; r++) {
        int m = m0 + ty + 4 * r;
        float v = acc[r];
        float hf;
        {
            uint32_t p = pack_bf16x2(v, 0.0f);
            hf = __uint_as_float(p << 16);
        }
        g_wbh[gate][s][m][tx] = __float2bfloat16(v);
        g_wbl[gate][s][m][tx] = __float2bfloat16(v - hf);
    }

    // fused bias, parallel: 4 partials (part = k-quarter) per output row
    __syncthreads();  // all reads of wx_s done -> reuse as scratch
    {
        const int mm = tid & 63, part = tid >> 6;
        const float* bxs  = bx + s * 256 + part * 64;
        const float* h0s  = h0 + s * 256 + part * 64;
        const float* rowh = WG + (size_t)(s * 256 + m0 + mm) * 512 + 256 + part * 64;
        const float* roww = wg_s + mm * 256 + part * 64;
        float p = 0.0f;
#pragma unroll 4
        for (int k = 0; k < 64; k++) {
            p += roww[k] * bxs[k];
        }
#pragma unroll 4
        for (int k = 0; k < 64; k++) {
            p += rowh[k] * h0s[k];
        }
        wx_s[part * 64 + mm] = p;
        __syncthreads();
        if (tid < 64) {
            float b = bG[s * 256 + m0 + tid] + wx_s[tid] + wx_s[64 + tid] +
                      wx_s[128 + tid] + wx_s[192 + tid];
            g_bias[gate][s][m0 + tid] = b;
        }
    }
}

// ---------------------------------------------------------------------------
// Kernel 2: main LSTM step via tensor cores (bf16 split GEMM + fused epilogue)
// grid = (token-tiles=128, m-octant=8, stream=8), block = 256 (8 warps)
// CTA tile: 128 tokens x (4 gates x 32 m).  Warp tile: 32 tokens x (4 gates x 16 m)
// smem: Ah[128][64] Al[128][64] Bh[128][64] Bl[128][64] bf16, swizzled = 64KB
// ---------------------------------------------------------------------------
__global__ __launch_bounds__(256, 2)
void lstm_mma_kernel(const float* __restrict__ mod,
                     const float* __restrict__ c0,
                     float* __restrict__ out) {
    extern __shared__ char sm[];
    char* smp = sm;
    const uint32_t AH = 0, AL = 16384, BH = 32768, BL = 49152;
    const uint32_t smbase = smem_u32(sm);

    const int s   = blockIdx.z;
    const int mq  = blockIdx.y;       // 32-m octant
    const int n0  = blockIdx.x * 128; // token base
    const int tid = threadIdx.x;

    // ---- stage A (tokens): fp32 -> bf16 hi/lo, swizzled ----
    for (int c = tid; c < 1024; c += 256) {
        int row = c >> 3, ck = c & 7;  // 16B chunk = 8 bf16 = 8 k-elems
        const float* src = mod + (size_t)(n0 + row) * (SS * II) + s * II + ck * 8;
        float4 v0 = *reinterpret_cast<const float4*>(src);
        float4 v1 = *reinterpret_cast<const float4*>(src + 4);
        float fv[8];
        fv[0] = v0.x; fv[1] = v0.y; fv[2] = v0.z; fv[3] = v0.w;
        fv[4] = v1.x; fv[5] = v1.y; fv[6] = v1.z; fv[7] = v1.w;
        uint32_t hp[4], lp[4];
#pragma unroll
        for (int j = 0; j < 4; j++) {
            float a = fv[2 * j], b = fv[2 * j + 1];
            uint32_t h = pack_bf16x2(a, b);
            float ha = __uint_as_float(h << 16);
            float hb = __uint_as_float(h & 0xFFFF0000u);
            hp[j] = h;
            lp[j] = pack_bf16x2(a - ha, b - hb);
        }
        uint32_t off = swz(row, ck * 16);
        *reinterpret_cast<uint4*>(smp + AH + off) = make_uint4(hp[0], hp[1], hp[2], hp[3]);
        *reinterpret_cast<uint4*>(smp + AL + off) = make_uint4(lp[0], lp[1], lp[2], lp[3]);
    }
    // ---- stage B (fused weights, bf16 hi/lo), rows r = gate*32 + m_local ----
    for (int c = tid; c < 1024; c += 256) {
        int r  = c >> 3;
        int ck = c & 7;
        int g  = r >> 5, ml = r & 31;
        uint32_t off = swz(r, ck * 16);
        *reinterpret_cast<uint4*>(smp + BH + off) =
            *reinterpret_cast<const uint4*>(&g_wbh[g][s][mq * 32 + ml][ck * 8]);
        *reinterpret_cast<uint4*>(smp + BL + off) =
            *reinterpret_cast<const uint4*>(&g_wbl[g][s][mq * 32 + ml][ck * 8]);
    }
    __syncthreads();

    // ---- mma mainloop ----
    const int w    = tid >> 5;
    const int lane = tid & 31;
    const int wr   = w >> 1;  // token row group (0..3)
    const int wc   = w & 1;   // m column group (0..1)
    const int lrow  = lane & 15;
    const int lcolb = (lane >> 4) * 16;

    float acc[2][4][2][4];  // [token-tile][gate][n-half][frag]
#pragma unroll
    for (int mt = 0; mt < 2; mt++) {
#pragma unroll
        for (int g = 0; g < 4; g++) {
#pragma unroll
            for (int h = 0; h < 2; h++) {
#pragma unroll
                for (int q = 0; q < 4; q++) {
                    acc[mt][g][h][q] = 0.0f;
                }
            }
        }
    }

    const uint32_t arow0 = wr * 32 + lrow;        // token-tile 0 rows
    const uint32_t arow1 = wr * 32 + 16 + lrow;   // token-tile 1 rows
    const uint32_t arb0 = arow0 * 128, arx0 = (arow0 & 7) << 4;
    const uint32_t arb1 = arow1 * 128, arx1 = (arow1 & 7) << 4;
    uint32_t brb[4], brx[4];
#pragma unroll
    for (int g = 0; g < 4; g++) {
        uint32_t brr = (uint32_t)(g * 32 + wc * 16) + (uint32_t)lrow;
        brb[g] = brr * 128;
        brx[g] = (brr & 7) << 4;
    }

#pragma unroll 1
    for (int v = 0; v < 3; v++) {
        // v0: Ah*Bh, v1: Al*Bh, v2: Ah*Bl
        const uint32_t ab = smbase + ((v == 1) ? AL : AH);
        const uint32_t bb = smbase + ((v == 2) ? BL : BH);
#pragma unroll
        for (int k = 0; k < 4; k++) {
            const uint32_t kc = (uint32_t)lcolb + (uint32_t)k * 32;
            uint32_t a0[4], a1[4];
            ldsm4(a0[0], a0[1], a0[2], a0[3], ab + arb0 + (kc ^ arx0));
            ldsm4(a1[0], a1[1], a1[2], a1[3], ab + arb1 + (kc ^ arx1));
            uint32_t bq[4][4];
#pragma unroll
            for (int g = 0; g < 4; g++) {
                ldsm4(bq[g][0], bq[g][1], bq[g][2], bq[g][3],
                      bb + brb[g] + (kc ^ brx[g]));
            }
#pragma unroll
            for (int g = 0; g < 4; g++) {
                mma16816(acc[0][g][0], a0, bq[g][0], bq[g][2]);
                mma16816(acc[0][g][1], a0, bq[g][1], bq[g][3]);
                mma16816(acc[1][g][0], a1, bq[g][0], bq[g][2]);
                mma16816(acc[1][g][1], a1, bq[g][1], bq[g][3]);
            }
        }
    }

    // ---- epilogue (all 4 gates live in this thread's registers) ----
    const int qrow = lane >> 2, qcol = lane & 3;
    const int mbase = mq * 32 + wc * 16;

    float bia[4][2][2];  // [gate][n-half][cp]
    float c0v[2][2];
#pragma unroll
    for (int h = 0; h < 2; h++) {
#pragma unroll
        for (int cp = 0; cp < 2; cp++) {
            int m = mbase + h * 8 + qcol * 2 + cp;
#pragma unroll
            for (int g = 0; g < 4; g++) {
                bia[g][h][cp] = g_bias[g][s][m];
            }
            c0v[h][cp] = c0[s * 256 + m];
        }
    }

#pragma unroll
    for (int mt = 0; mt < 2; mt++) {
#pragma unroll
        for (int rp = 0; rp < 2; rp++) {
            int token = n0 + wr * 32 + mt * 16 + qrow + rp * 8;
#pragma unroll
            for (int h = 0; h < 2; h++) {
                float hv0, hv1;
#pragma unroll
                for (int cp = 0; cp < 2; cp++) {
                    int idx = rp * 2 + cp;
                    float iv = sigmoid_f(acc[mt][0][h][idx] + bia[0][h][cp]);
                    float fv = sigmoid_f(acc[mt][1][h][idx] + bia[1][h][cp]);
                    float gv = tanh_f(acc[mt][2][h][idx] + bia[2][h][cp]);
                    float ov = sigmoid_f(acc[mt][3][h][idx] + bia[3][h][cp]);
                    float cc = fv * c0v[h][cp] + iv * gv;
                    float hh = ov * tanh_f(cc);
                    if (cp == 0) { hv0 = hh; } else { hv1 = hh; }
                }
                float2 hv;
                hv.x = hv0;
                hv.y = hv1;
                *reinterpret_cast<float2*>(
                    out + (size_t)token * (SS * MM) + s * 256 + mbase + h * 8 + qcol * 2) = hv;
            }
        }
    }
}

// ---------------------------------------------------------------------------
// launch
// ---------------------------------------------------------------------------
extern "C" void kernel_launch(void* const* d_in, const int* in_sizes, int n_in,
                              void* d_out, int out_size) {
    const float* mod = (const float*)d_in[0];
    const float* h0  = (const float*)d_in[1];
    const float* c0  = (const float*)d_in[2];
    const float* Wx  = (const float*)d_in[3];
    const float* bx  = (const float*)d_in[4];
    const float* Wi  = (const float*)d_in[5];
    const float* bi  = (const float*)d_in[6];
    const float* Wf  = (const float*)d_in[7];
    const float* bf  = (const float*)d_in[8];
    const float* Wg  = (const float*)d_in[9];
    const float* bg  = (const float*)d_in[10];
    const float* Wo  = (const float*)d_in[11];
    const float* bo  = (const float*)d_in[12];
    float* out = (float*)d_out;

    cudaFuncSetAttribute(precompute_kernel,
                         cudaFuncAttributeMaxDynamicSharedMemorySize, 131072);
    cudaFuncSetAttribute(lstm_mma_kernel,
                         cudaFuncAttributeMaxDynamicSharedMemorySize, 65536);

    precompute_kernel<<<dim3(SS, 4, 4), 256, 131072>>>(
        Wx, bx, Wi, bi, Wf, bf, Wg, bg, Wo, bo, h0);

    lstm_mma_kernel<<<dim3(NTOK / 128, 8, SS), 256, 65536>>>(mod, c0, out);
}

// round 6
// speedup vs baseline: 3.3925x; 1.1788x over previous
#include <cuda_runtime.h>
#include <cuda_bf16.h>
#include <cstdint>

// Problem constants
#define SS 8        // streams
#define II 64       // modulations per stream
#define MM 256      // features per stream
#define NTOK 16384  // batch

// Fused weights (bf16 hi/lo split): W~_g[s] = Wg[:, :, 0:M] @ Wx[s]  -> [4][S][M][64]
__device__ __nv_bfloat16 g_wbh[4][SS][MM][II];
__device__ __nv_bfloat16 g_wbl[4][SS][MM][II];
// Fused biases:  b~_g[s,m] = bg + Wg_x@bx + Wg_h@h0
__device__ float g_bias[4][SS][MM];

// ---------------------------------------------------------------------------
// helpers
// ---------------------------------------------------------------------------
__device__ __forceinline__ float sigmoid_f(float x) {
    float e = __expf(-x);
    return __fdividef(1.0f, 1.0f + e);
}
__device__ __forceinline__ float tanh_f(float x) {
    float e = __expf(-2.0f * x);
    return __fdividef(2.0f, 1.0f + e) - 1.0f;
}

// pack two floats into bf16x2 (lo in low half)
__device__ __forceinline__ uint32_t pack_bf16x2(float lo, float hi) {
    uint32_t r;
    asm("cvt.rn.bf16x2.f32 %0, %1, %2;" : "=r"(r) : "f"(hi), "f"(lo));
    return r;
}

__device__ __forceinline__ uint32_t smem_u32(const void* p) {
    uint32_t a;
    asm("{ .reg .u64 t; cvta.to.shared.u64 t, %1; cvt.u32.u64 %0, t; }"
        : "=r"(a) : "l"(p));
    return a;
}

__device__ __forceinline__ void ldsm4(uint32_t& r0, uint32_t& r1,
                                      uint32_t& r2, uint32_t& r3, uint32_t addr) {
    asm volatile("ldmatrix.sync.aligned.m8n8.x4.shared.b16 {%0,%1,%2,%3}, [%4];"
                 : "=r"(r0), "=r"(r1), "=r"(r2), "=r"(r3) : "r"(addr));
}

__device__ __forceinline__ void mma16816(float* c, const uint32_t* a,
                                         uint32_t b0, uint32_t b1) {
    asm volatile(
        "mma.sync.aligned.m16n8k16.row.col.f32.bf16.bf16.f32 "
        "{%0,%1,%2,%3}, {%4,%5,%6,%7}, {%8,%9}, {%0,%1,%2,%3};"
        : "+f"(c[0]), "+f"(c[1]), "+f"(c[2]), "+f"(c[3])
        : "r"(a[0]), "r"(a[1]), "r"(a[2]), "r"(a[3]), "r"(b0), "r"(b1));
}

// swizzled smem byte offset for rows of 128B: XOR 16B-chunk by (row&7)
__device__ __forceinline__ uint32_t swz(uint32_t row, uint32_t colbyte) {
    return row * 128u + (colbyte ^ ((row & 7u) << 4));
}

#define CP_ASYNC16(dst, gsrc) \
    asm volatile("cp.async.cg.shared.global [%0], [%1], 16;" \
                 :: "r"(dst), "l"(gsrc) : "memory")
#define CP_COMMIT() asm volatile("cp.async.commit_group;" ::: "memory")
#define CP_WAIT0()  asm volatile("cp.async.wait_group 0;" ::: "memory")

// ---------------------------------------------------------------------------
// Kernel 1: weight/bias fusion
// grid = (S, 4 gates, 8 m-blocks of 32), block = 256
// smem: wx_s[256*64] (64KB) + wg_s[32*256] (32KB)
// ---------------------------------------------------------------------------
__global__ __launch_bounds__(256, 1)
void precompute_kernel(const float* __restrict__ Wx, const float* __restrict__ bx,
                       const float* __restrict__ Wi, const float* __restrict__ bi,
                       const float* __restrict__ Wf, const float* __restrict__ bf,
                       const float* __restrict__ Wg, const float* __restrict__ bg,
                       const float* __restrict__ Wo, const float* __restrict__ bo,
                       const float* __restrict__ h0) {
    extern __shared__ float smem[];
    float* wx_s = smem;            // [k=256][i=64]
    float* wg_s = smem + 256 * 64; // [mm=32][k=256]

    const int s    = blockIdx.x;
    const int gate = blockIdx.y;
    const int m0   = blockIdx.z * 32;
    const int tid  = threadIdx.x;

    const float* WG;
    const float* bG;
    switch (gate) {
        case 0:  WG = Wi; bG = bi; break;
        case 1:  WG = Wf; bG = bf; break;
        case 2:  WG = Wg; bG = bg; break;
        default: WG = Wo; bG = bo; break;
    }

    for (int idx = tid; idx < 256 * 64; idx += 256) {
        wx_s[idx] = Wx[(size_t)s * 256 * 64 + idx];
    }
    for (int idx = tid; idx < 32 * 256; idx += 256) {
        int mm = idx >> 8, k = idx & 255;
        wg_s[idx] = WG[(size_t)(s * 256 + m0 + mm) * 512 + k];
    }
    __syncthreads();

    const int tx = tid & 63;  // i column
    const int ty = tid >> 6;  // 0..3

    float acc[8];
#pragma unroll
    for (int r = 0; r < 8; r++) {
        acc[r] = 0.0f;
    }

    for (int k = 0; k < 256; k += 4) {
        float x0 = wx_s[(k + 0) * 64 + tx];
        float x1 = wx_s[(k + 1) * 64 + tx];
        float x2 = wx_s[(k + 2) * 64 + tx];
        float x3 = wx_s[(k + 3) * 64 + tx];
#pragma unroll
        for (int r = 0; r < 8; r++) {
            int ml = ty + 4 * r;
            float4 wv = *reinterpret_cast<const float4*>(&wg_s[ml * 256 + k]);
            acc[r] += wv.x * x0;
            acc[r] += wv.y * x1;
            acc[r] += wv.z * x2;
            acc[r] += wv.w * x3;
        }
    }
#pragma unroll
    for (int r = 0; r < 8; r++) {
        int m = m0 + ty + 4 * r;
        float v = acc[r];
        uint32_t p = pack_bf16x2(v, 0.0f);
        float hf = __uint_as_float(p << 16);
        g_wbh[gate][s][m][tx] = __float2bfloat16(v);
        g_wbl[gate][s][m][tx] = __float2bfloat16(v - hf);
    }

    // fused bias: 8 partials of 64 per output row (rows of 32)
    __syncthreads();  // all reads of wx_s done -> reuse as scratch
    {
        const int mm = tid & 31, part = tid >> 5;
        float p = 0.0f;
        if (part < 4) {
            const float* a = wg_s + mm * 256 + part * 64;
            const float* b = bx + s * 256 + part * 64;
#pragma unroll 4
            for (int k = 0; k < 64; k++) {
                p += a[k] * b[k];
            }
        } else {
            const float* a = WG + (size_t)(s * 256 + m0 + mm) * 512 + 256 + (part - 4) * 64;
            const float* b = h0 + s * 256 + (part - 4) * 64;
#pragma unroll 4
            for (int k = 0; k < 64; k++) {
                p += a[k] * b[k];
            }
        }
        wx_s[part * 32 + mm] = p;
        __syncthreads();
        if (tid < 32) {
            float b = bG[s * 256 + m0 + tid];
#pragma unroll
            for (int j = 0; j < 8; j++) {
                b += wx_s[j * 32 + tid];
            }
            g_bias[gate][s][m0 + tid] = b;
        }
    }
}

// ---------------------------------------------------------------------------
// Kernel 2: main LSTM step (mma.sync bf16 split GEMM, persistent over m-octants)
// grid = (token-tiles=128, 1, stream=8) = 1024 CTAs, block = 256 (8 warps)
// Per CTA: stage A once (128 tokens, hi/lo), then loop mq=0..7:
//   B[mq] arrives via double-buffered cp.async; fused 3-pass mainloop; epilogue.
// smem: Ah(16K) Al(16K) + 2 x (Bh(16K)+Bl(16K)) = 96KB
// ---------------------------------------------------------------------------
#define SM_AH 0u
#define SM_AL 16384u
#define SM_B0 32768u     // buffer p at SM_B0 + p*32768 (H), +16384 (L)
#define SM_SZ 98304u

__global__ __launch_bounds__(256, 2)
void lstm_mma_kernel(const float* __restrict__ mod,
                     const float* __restrict__ c0,
                     float* __restrict__ out) {
    extern __shared__ char sm[];
    char* smp = sm;
    const uint32_t smbase = smem_u32(sm);

    const int s   = blockIdx.z;
    const int n0  = blockIdx.x * 128; // token base
    const int tid = threadIdx.x;

    // ---- stage A (tokens): fp32 -> bf16 hi/lo, SW128 (once per CTA) ----
    for (int c = tid; c < 1024; c += 256) {
        int row = c >> 3, ck = c & 7;  // 16B chunk = 8 bf16
        const float* src = mod + (size_t)(n0 + row) * (SS * II) + s * II + ck * 8;
        float4 v0 = *reinterpret_cast<const float4*>(src);
        float4 v1 = *reinterpret_cast<const float4*>(src + 4);
        float fv[8];
        fv[0] = v0.x; fv[1] = v0.y; fv[2] = v0.z; fv[3] = v0.w;
        fv[4] = v1.x; fv[5] = v1.y; fv[6] = v1.z; fv[7] = v1.w;
        uint32_t hp[4], lp[4];
#pragma unroll
        for (int j = 0; j < 4; j++) {
            float a = fv[2 * j], b = fv[2 * j + 1];
            uint32_t h = pack_bf16x2(a, b);
            float ha = __uint_as_float(h << 16);
            float hb = __uint_as_float(h & 0xFFFF0000u);
            hp[j] = h;
            lp[j] = pack_bf16x2(a - ha, b - hb);
        }
        uint32_t off = swz((uint32_t)row, (uint32_t)ck * 16);
        *reinterpret_cast<uint4*>(smp + SM_AH + off) = make_uint4(hp[0], hp[1], hp[2], hp[3]);
        *reinterpret_cast<uint4*>(smp + SM_AL + off) = make_uint4(lp[0], lp[1], lp[2], lp[3]);
    }

    // ---- kick off B[0] via cp.async into buffer 0 ----
    for (int c = tid; c < 1024; c += 256) {
        int r = c >> 3, ck = c & 7;
        int g = r >> 5, ml = r & 31;
        uint32_t off = swz((uint32_t)r, (uint32_t)ck * 16);
        CP_ASYNC16(smbase + SM_B0 + off,
                   __cvta_generic_to_global(&g_wbh[g][s][ml][ck * 8]));
        CP_ASYNC16(smbase + SM_B0 + 16384u + off,
                   __cvta_generic_to_global(&g_wbl[g][s][ml][ck * 8]));
    }
    CP_COMMIT();

    // ---- warp/lane geometry ----
    const int w    = tid >> 5;
    const int lane = tid & 31;
    const int wr   = w >> 1;  // token row group (0..3)
    const int wc   = w & 1;   // m column group (0..1)
    const int lrow  = lane & 15;
    const int lcolb = (lane >> 4) * 16;

    const uint32_t arow0 = (uint32_t)(wr * 32 + lrow);
    const uint32_t arow1 = (uint32_t)(wr * 32 + 16 + lrow);
    const uint32_t arb0 = arow0 * 128, arx0 = (arow0 & 7) << 4;
    const uint32_t arb1 = arow1 * 128, arx1 = (arow1 & 7) << 4;
    uint32_t brb[4], brx[4];
#pragma unroll
    for (int g = 0; g < 4; g++) {
        uint32_t brr = (uint32_t)(g * 32 + wc * 16) + (uint32_t)lrow;
        brb[g] = brr * 128;
        brx[g] = (brr & 7) << 4;
    }
    const uint32_t abh = smbase + SM_AH;
    const uint32_t abl = smbase + SM_AL;

    const int qrow = lane >> 2, qcol = lane & 3;

#pragma unroll 1
    for (int mq = 0; mq < 8; mq++) {
        const int p = mq & 1;

        CP_WAIT0();
        __syncthreads();

        // prefetch B[mq+1] into the other buffer (overlaps with mainloop)
        if (mq < 7) {
            const int mn = mq + 1;
            const uint32_t bufb = smbase + SM_B0 + (uint32_t)(1 - p) * 32768u;
            for (int c = tid; c < 1024; c += 256) {
                int r = c >> 3, ck = c & 7;
                int g = r >> 5, ml = r & 31;
                uint32_t off = swz((uint32_t)r, (uint32_t)ck * 16);
                CP_ASYNC16(bufb + off,
                           __cvta_generic_to_global(&g_wbh[g][s][mn * 32 + ml][ck * 8]));
                CP_ASYNC16(bufb + 16384u + off,
                           __cvta_generic_to_global(&g_wbl[g][s][mn * 32 + ml][ck * 8]));
            }
            CP_COMMIT();
        }

        const uint32_t bbh = smbase + SM_B0 + (uint32_t)p * 32768u;
        const uint32_t bbl = bbh + 16384u;

        float acc[2][4][2][4];  // [token-tile][gate][n-half][frag]
#pragma unroll
        for (int mt = 0; mt < 2; mt++) {
#pragma unroll
            for (int g = 0; g < 4; g++) {
#pragma unroll
                for (int h = 0; h < 2; h++) {
#pragma unroll
                    for (int q = 0; q < 4; q++) {
                        acc[mt][g][h][q] = 0.0f;
                    }
                }
            }
        }

        // ---- fused 3-pass mainloop: operands loaded once per k-step ----
#pragma unroll
        for (int k = 0; k < 4; k++) {
            const uint32_t kc = (uint32_t)lcolb + (uint32_t)k * 32;
            uint32_t a0h[4], a1h[4], a0l[4], a1l[4];
            ldsm4(a0h[0], a0h[1], a0h[2], a0h[3], abh + arb0 + (kc ^ arx0));
            ldsm4(a1h[0], a1h[1], a1h[2], a1h[3], abh + arb1 + (kc ^ arx1));
            ldsm4(a0l[0], a0l[1], a0l[2], a0l[3], abl + arb0 + (kc ^ arx0));
            ldsm4(a1l[0], a1l[1], a1l[2], a1l[3], abl + arb1 + (kc ^ arx1));
#pragma unroll
            for (int gp = 0; gp < 2; gp++) {
                uint32_t bh[2][4], bl[2][4];
#pragma unroll
                for (int g2 = 0; g2 < 2; g2++) {
                    int g = gp * 2 + g2;
                    ldsm4(bh[g2][0], bh[g2][1], bh[g2][2], bh[g2][3],
                          bbh + brb[g] + (kc ^ brx[g]));
                    ldsm4(bl[g2][0], bl[g2][1], bl[g2][2], bl[g2][3],
                          bbl + brb[g] + (kc ^ brx[g]));
                }
#pragma unroll
                for (int g2 = 0; g2 < 2; g2++) {
                    int g = gp * 2 + g2;
                    mma16816(acc[0][g][0], a0h, bh[g2][0], bh[g2][2]);
                    mma16816(acc[0][g][1], a0h, bh[g2][1], bh[g2][3]);
                    mma16816(acc[1][g][0], a1h, bh[g2][0], bh[g2][2]);
                    mma16816(acc[1][g][1], a1h, bh[g2][1], bh[g2][3]);
                    mma16816(acc[0][g][0], a0l, bh[g2][0], bh[g2][2]);
                    mma16816(acc[0][g][1], a0l, bh[g2][1], bh[g2][3]);
                    mma16816(acc[1][g][0], a1l, bh[g2][0], bh[g2][2]);
                    mma16816(acc[1][g][1], a1l, bh[g2][1], bh[g2][3]);
                    mma16816(acc[0][g][0], a0h, bl[g2][0], bl[g2][2]);
                    mma16816(acc[0][g][1], a0h, bl[g2][1], bl[g2][3]);
                    mma16816(acc[1][g][0], a1h, bl[g2][0], bl[g2][2]);
                    mma16816(acc[1][g][1], a1h, bl[g2][1], bl[g2][3]);
                }
            }
        }

        // ---- epilogue (all 4 gates live in this thread's registers) ----
        const int mbase = mq * 32 + wc * 16;

        float bia[4][2][2];  // [gate][n-half][cp]
        float c0v[2][2];
#pragma unroll
        for (int h = 0; h < 2; h++) {
#pragma unroll
            for (int cp = 0; cp < 2; cp++) {
                int m = mbase + h * 8 + qcol * 2 + cp;
#pragma unroll
                for (int g = 0; g < 4; g++) {
                    bia[g][h][cp] = g_bias[g][s][m];
                }
                c0v[h][cp] = c0[s * 256 + m];
            }
        }

#pragma unroll
        for (int mt = 0; mt < 2; mt++) {
#pragma unroll
            for (int rp = 0; rp < 2; rp++) {
                int token = n0 + wr * 32 + mt * 16 + qrow + rp * 8;
#pragma unroll
                for (int h = 0; h < 2; h++) {
                    float hv0, hv1;
#pragma unroll
                    for (int cp = 0; cp < 2; cp++) {
                        int idx = rp * 2 + cp;
                        float iv = sigmoid_f(acc[mt][0][h][idx] + bia[0][h][cp]);
                        float fv = sigmoid_f(acc[mt][1][h][idx] + bia[1][h][cp]);
                        float gv = tanh_f(acc[mt][2][h][idx] + bia[2][h][cp]);
                        float ov = sigmoid_f(acc[mt][3][h][idx] + bia[3][h][cp]);
                        float cc = fv * c0v[h][cp] + iv * gv;
                        float hh = ov * tanh_f(cc);
                        if (cp == 0) { hv0 = hh; } else { hv1 = hh; }
                    }
                    float2 hv;
                    hv.x = hv0;
                    hv.y = hv1;
                    *reinterpret_cast<float2*>(
                        out + (size_t)token * (SS * MM) + s * 256 + mbase + h * 8 + qcol * 2) = hv;
                }
            }
        }
    }
}

// ---------------------------------------------------------------------------
// launch
// ---------------------------------------------------------------------------
extern "C" void kernel_launch(void* const* d_in, const int* in_sizes, int n_in,
                              void* d_out, int out_size) {
    const float* mod = (const float*)d_in[0];
    const float* h0  = (const float*)d_in[1];
    const float* c0  = (const float*)d_in[2];
    const float* Wx  = (const float*)d_in[3];
    const float* bx  = (const float*)d_in[4];
    const float* Wi  = (const float*)d_in[5];
    const float* bi  = (const float*)d_in[6];
    const float* Wf  = (const float*)d_in[7];
    const float* bf  = (const float*)d_in[8];
    const float* Wg  = (const float*)d_in[9];
    const float* bg  = (const float*)d_in[10];
    const float* Wo  = (const float*)d_in[11];
    const float* bo  = (const float*)d_in[12];
    float* out = (float*)d_out;

    cudaFuncSetAttribute(precompute_kernel,
                         cudaFuncAttributeMaxDynamicSharedMemorySize, 98304);
    cudaFuncSetAttribute(lstm_mma_kernel,
                         cudaFuncAttributeMaxDynamicSharedMemorySize, SM_SZ);

    precompute_kernel<<<dim3(SS, 4, 8), 256, 98304>>>(
        Wx, bx, Wi, bi, Wf, bf, Wg, bg, Wo, bo, h0);

    lstm_mma_kernel<<<dim3(NTOK / 128, 1, SS), 256, SM_SZ>>>(mod, c0, out);
}

// round 7
// speedup vs baseline: 3.4097x; 1.0051x over previous
#include <cuda_runtime.h>
#include <cuda_bf16.h>
#include <cstdint>

// Problem constants
#define SS 8        // streams
#define II 64       // modulations per stream
#define MM 256      // features per stream
#define NTOK 16384  // batch

// Fused weights (bf16 hi/lo split): W~_g[s] = Wg[:, :, 0:M] @ Wx[s]  -> [4][S][M][64]
__device__ __nv_bfloat16 g_wbh[4][SS][MM][II];
__device__ __nv_bfloat16 g_wbl[4][SS][MM][II];
// Fused biases:  b~_g[s,m] = bg + Wg_x@bx + Wg_h@h0
__device__ float g_bias[4][SS][MM];

// ---------------------------------------------------------------------------
// helpers
// ---------------------------------------------------------------------------
__device__ __forceinline__ float sigmoid_f(float x) {
    float e = __expf(-x);
    return __fdividef(1.0f, 1.0f + e);
}
__device__ __forceinline__ float tanh_f(float x) {
    float e = __expf(-2.0f * x);
    return __fdividef(2.0f, 1.0f + e) - 1.0f;
}

// pack two floats into bf16x2 (lo in low half)
__device__ __forceinline__ uint32_t pack_bf16x2(float lo, float hi) {
    uint32_t r;
    asm("cvt.rn.bf16x2.f32 %0, %1, %2;" : "=r"(r) : "f"(hi), "f"(lo));
    return r;
}

__device__ __forceinline__ uint32_t smem_u32(const void* p) {
    uint32_t a;
    asm("{ .reg .u64 t; cvta.to.shared.u64 t, %1; cvt.u32.u64 %0, t; }"
        : "=r"(a) : "l"(p));
    return a;
}

__device__ __forceinline__ void ldsm4(uint32_t& r0, uint32_t& r1,
                                      uint32_t& r2, uint32_t& r3, uint32_t addr) {
    asm volatile("ldmatrix.sync.aligned.m8n8.x4.shared.b16 {%0,%1,%2,%3}, [%4];"
                 : "=r"(r0), "=r"(r1), "=r"(r2), "=r"(r3) : "r"(addr));
}

__device__ __forceinline__ void mma16816(float* c, const uint32_t* a,
                                         uint32_t b0, uint32_t b1) {
    asm volatile(
        "mma.sync.aligned.m16n8k16.row.col.f32.bf16.bf16.f32 "
        "{%0,%1,%2,%3}, {%4,%5,%6,%7}, {%8,%9}, {%0,%1,%2,%3};"
        : "+f"(c[0]), "+f"(c[1]), "+f"(c[2]), "+f"(c[3])
        : "r"(a[0]), "r"(a[1]), "r"(a[2]), "r"(a[3]), "r"(b0), "r"(b1));
}

// swizzled smem byte offset for rows of 128B: XOR 16B-chunk by (row&7)
__device__ __forceinline__ uint32_t swz(uint32_t row, uint32_t colbyte) {
    return row * 128u + (colbyte ^ ((row & 7u) << 4));
}

#define CP_ASYNC16(dst, gsrc) \
    asm volatile("cp.async.cg.shared.global [%0], [%1], 16;" \
                 :: "r"(dst), "l"(gsrc) : "memory")

#define MBAR_INIT(addr, cnt) \
    asm volatile("mbarrier.init.shared.b64 [%0], %1;" :: "r"(addr), "r"(cnt) : "memory")
#define MBAR_ARRIVE(addr) \
    asm volatile("mbarrier.arrive.shared.b64 _, [%0];" :: "r"(addr) : "memory")
#define CP_ASYNC_MBAR_ARRIVE_NOINC(addr) \
    asm volatile("cp.async.mbarrier.arrive.noinc.shared::cta.b64 [%0];" :: "r"(addr) : "memory")

#define MBAR_WAIT_PARITY(addr, par) do {                                        \
    uint32_t _mb = (addr);                                                      \
    uint32_t _pa = (par);                                                       \
    uint32_t _done;                                                             \
    asm volatile(                                                               \
        "{\n\t"                                                                 \
        ".reg .pred p;\n\t"                                                     \
        "mbarrier.try_wait.parity.acquire.cta.shared::cta.b64 p, [%1], %2;\n\t" \
        "selp.b32 %0, 1, 0, p;\n\t"                                             \
        "}" : "=r"(_done) : "r"(_mb), "r"(_pa) : "memory");                     \
    if (!_done) {                                                               \
        asm volatile(                                                           \
            "{\n\t"                                                             \
            ".reg .pred P1;\n\t"                                                \
            "WL_%=:\n\t"                                                        \
            "mbarrier.try_wait.parity.acquire.cta.shared::cta.b64 P1, [%0], %1, 0x989680;\n\t" \
            "@P1 bra.uni WD_%=;\n\t"                                            \
            "bra.uni WL_%=;\n\t"                                                \
            "WD_%=:\n\t"                                                        \
            "}" :: "r"(_mb), "r"(_pa) : "memory");                              \
    }                                                                           \
} while (0)

// ---------------------------------------------------------------------------
// Kernel 1: weight/bias fusion
// grid = (S, 4 gates, 8 m-blocks of 32), block = 256
// smem: wx_s[256*64] (64KB) + wg_s[32*256] (32KB)
// ---------------------------------------------------------------------------
__global__ __launch_bounds__(256, 1)
void precompute_kernel(const float* __restrict__ Wx, const float* __restrict__ bx,
                       const float* __restrict__ Wi, const float* __restrict__ bi,
                       const float* __restrict__ Wf, const float* __restrict__ bf,
                       const float* __restrict__ Wg, const float* __restrict__ bg,
                       const float* __restrict__ Wo, const float* __restrict__ bo,
                       const float* __restrict__ h0) {
    extern __shared__ float smem[];
    float* wx_s = smem;            // [k=256][i=64]
    float* wg_s = smem + 256 * 64; // [mm=32][k=256]

    const int s    = blockIdx.x;
    const int gate = blockIdx.y;
    const int m0   = blockIdx.z * 32;
    const int tid  = threadIdx.x;

    const float* WG;
    const float* bG;
    switch (gate) {
        case 0:  WG = Wi; bG = bi; break;
        case 1:  WG = Wf; bG = bf; break;
        case 2:  WG = Wg; bG = bg; break;
        default: WG = Wo; bG = bo; break;
    }

    for (int idx = tid; idx < 256 * 64; idx += 256) {
        wx_s[idx] = Wx[(size_t)s * 256 * 64 + idx];
    }
    for (int idx = tid; idx < 32 * 256; idx += 256) {
        int mm = idx >> 8, k = idx & 255;
        wg_s[idx] = WG[(size_t)(s * 256 + m0 + mm) * 512 + k];
    }
    __syncthreads();

    const int tx = tid & 63;  // i column
    const int ty = tid >> 6;  // 0..3

    float acc[8];
#pragma unroll
    for (int r = 0; r < 8; r++) {
        acc[r] = 0.0f;
    }

    for (int k = 0; k < 256; k += 4) {
        float x0 = wx_s[(k + 0) * 64 + tx];
        float x1 = wx_s[(k + 1) * 64 + tx];
        float x2 = wx_s[(k + 2) * 64 + tx];
        float x3 = wx_s[(k + 3) * 64 + tx];
#pragma unroll
        for (int r = 0; r < 8; r++) {
            int ml = ty + 4 * r;
            float4 wv = *reinterpret_cast<const float4*>(&wg_s[ml * 256 + k]);
            acc[r] += wv.x * x0;
            acc[r] += wv.y * x1;
            acc[r] += wv.z * x2;
            acc[r] += wv.w * x3;
        }
    }
#pragma unroll
    for (int r = 0; r < 8; r++) {
        int m = m0 + ty + 4 * r;
        float v = acc[r];
        uint32_t p = pack_bf16x2(v, 0.0f);
        float hf = __uint_as_float(p << 16);
        g_wbh[gate][s][m][tx] = __float2bfloat16(v);
        g_wbl[gate][s][m][tx] = __float2bfloat16(v - hf);
    }

    // fused bias: 8 partials of 64 per output row (rows of 32)
    __syncthreads();  // all reads of wx_s done -> reuse as scratch
    {
        const int mm = tid & 31, part = tid >> 5;
        float p = 0.0f;
        if (part < 4) {
            const float* a = wg_s + mm * 256 + part * 64;
            const float* b = bx + s * 256 + part * 64;
#pragma unroll 4
            for (int k = 0; k < 64; k++) {
                p += a[k] * b[k];
            }
        } else {
            const float* a = WG + (size_t)(s * 256 + m0 + mm) * 512 + 256 + (part - 4) * 64;
            const float* b = h0 + s * 256 + (part - 4) * 64;
#pragma unroll 4
            for (int k = 0; k < 64; k++) {
                p += a[k] * b[k];
            }
        }
        wx_s[part * 32 + mm] = p;
        __syncthreads();
        if (tid < 32) {
            float b = bG[s * 256 + m0 + tid];
#pragma unroll
            for (int j = 0; j < 8; j++) {
                b += wx_s[j * 32 + tid];
            }
            g_bias[gate][s][m0 + tid] = b;
        }
    }
}

// ---------------------------------------------------------------------------
// Kernel 2: main LSTM step (mma.sync bf16 split GEMM, persistent over m-octants,
// mbarrier-pipelined B buffers so epilogue(MUFU) overlaps mainloop(HMMA) across warps)
// grid = (token-tiles=128, 1, stream=8) = 1024 CTAs, block = 256 (8 warps)
// smem: Ah(16K) Al(16K) + 2 x (Bh(16K)+Bl(16K)) + bias(4K) + c0(1K) + mbarriers
// ---------------------------------------------------------------------------
#define SM_AH   0u
#define SM_AL   16384u
#define SM_BB   32768u     // buffer p at SM_BB + p*32768 (H), +16384 (L)
#define SM_BIAS 98304u     // 1024 floats
#define SM_C0   102400u    // 256 floats
#define SM_MB   103424u    // full0, full1, rd0, rd1 (8B each)
#define SM_SZ   103456u

__global__ __launch_bounds__(256, 2)
void lstm_mma_kernel(const float* __restrict__ mod,
                     const float* __restrict__ c0,
                     float* __restrict__ out) {
    extern __shared__ char sm[];
    char* smp = sm;
    const uint32_t smbase = smem_u32(sm);

    const int s   = blockIdx.z;
    const int n0  = blockIdx.x * 128; // token base
    const int tid = threadIdx.x;

    const uint32_t mb_full[2] = {smbase + SM_MB, smbase + SM_MB + 8};
    const uint32_t mb_rd[2]   = {smbase + SM_MB + 16, smbase + SM_MB + 24};

    if (tid == 0) {
        MBAR_INIT(mb_full[0], 256);
        MBAR_INIT(mb_full[1], 256);
        MBAR_INIT(mb_rd[0], 256);
        MBAR_INIT(mb_rd[1], 256);
    }
    __syncthreads();

    // ---- kick off B[0] via cp.async into buffer 0, tracked by full[0] ----
    for (int c = tid; c < 1024; c += 256) {
        int r = c >> 3, ck = c & 7;
        int g = r >> 5, ml = r & 31;
        uint32_t off = swz((uint32_t)r, (uint32_t)ck * 16);
        CP_ASYNC16(smbase + SM_BB + off,
                   __cvta_generic_to_global(&g_wbh[g][s][ml][ck * 8]));
        CP_ASYNC16(smbase + SM_BB + 16384u + off,
                   __cvta_generic_to_global(&g_wbl[g][s][ml][ck * 8]));
    }
    CP_ASYNC_MBAR_ARRIVE_NOINC(mb_full[0]);

    // ---- stage A (tokens): fp32 -> bf16 hi/lo, SW128 (overlaps B0 copy) ----
    for (int c = tid; c < 1024; c += 256) {
        int row = c >> 3, ck = c & 7;  // 16B chunk = 8 bf16
        const float* src = mod + (size_t)(n0 + row) * (SS * II) + s * II + ck * 8;
        float4 v0 = *reinterpret_cast<const float4*>(src);
        float4 v1 = *reinterpret_cast<const float4*>(src + 4);
        float fv[8];
        fv[0] = v0.x; fv[1] = v0.y; fv[2] = v0.z; fv[3] = v0.w;
        fv[4] = v1.x; fv[5] = v1.y; fv[6] = v1.z; fv[7] = v1.w;
        uint32_t hp[4], lp[4];
#pragma unroll
        for (int j = 0; j < 4; j++) {
            float a = fv[2 * j], b = fv[2 * j + 1];
            uint32_t h = pack_bf16x2(a, b);
            float ha = __uint_as_float(h << 16);
            float hb = __uint_as_float(h & 0xFFFF0000u);
            hp[j] = h;
            lp[j] = pack_bf16x2(a - ha, b - hb);
        }
        uint32_t off = swz((uint32_t)row, (uint32_t)ck * 16);
        *reinterpret_cast<uint4*>(smp + SM_AH + off) = make_uint4(hp[0], hp[1], hp[2], hp[3]);
        *reinterpret_cast<uint4*>(smp + SM_AL + off) = make_uint4(lp[0], lp[1], lp[2], lp[3]);
    }

    // ---- stage biases + c0 into smem ----
    for (int i = tid; i < 1024; i += 256) {
        int g = i >> 8, m = i & 255;
        *reinterpret_cast<float*>(smp + SM_BIAS + i * 4) = g_bias[g][s][m];
    }
    *reinterpret_cast<float*>(smp + SM_C0 + tid * 4) = c0[s * 256 + tid];
    __syncthreads();  // A + bias/c0 visible CTA-wide

    // ---- warp/lane geometry ----
    const int w    = tid >> 5;
    const int lane = tid & 31;
    const int wr   = w >> 1;  // token row group (0..3)
    const int wc   = w & 1;   // m column group (0..1)
    const int lrow  = lane & 15;
    const int lcolb = (lane >> 4) * 16;

    const uint32_t arow0 = (uint32_t)(wr * 32 + lrow);
    const uint32_t arow1 = (uint32_t)(wr * 32 + 16 + lrow);
    const uint32_t arb0 = arow0 * 128, arx0 = (arow0 & 7) << 4;
    const uint32_t arb1 = arow1 * 128, arx1 = (arow1 & 7) << 4;
    uint32_t brb[4], brx[4];
#pragma unroll
    for (int g = 0; g < 4; g++) {
        uint32_t brr = (uint32_t)(g * 32 + wc * 16) + (uint32_t)lrow;
        brb[g] = brr * 128;
        brx[g] = (brr & 7) << 4;
    }
    const uint32_t abh = smbase + SM_AH;
    const uint32_t abl = smbase + SM_AL;

    const int qrow = lane >> 2, qcol = lane & 3;
    const float* bias_s = reinterpret_cast<const float*>(smp + SM_BIAS);
    const float* c0_s   = reinterpret_cast<const float*>(smp + SM_C0);

#pragma unroll 1
    for (int mq = 0; mq < 8; mq++) {
        const int p = mq & 1;
        const uint32_t bbh = smbase + SM_BB + (uint32_t)p * 32768u;
        const uint32_t bbl = bbh + 16384u;

        // wait B[mq] data ready
        MBAR_WAIT_PARITY(mb_full[p], (uint32_t)((mq >> 1) & 1));

        float acc[2][4][2][4];  // [token-tile][gate][n-half][frag]
#pragma unroll
        for (int mt = 0; mt < 2; mt++) {
#pragma unroll
            for (int g = 0; g < 4; g++) {
#pragma unroll
                for (int h = 0; h < 2; h++) {
#pragma unroll
                    for (int q = 0; q < 4; q++) {
                        acc[mt][g][h][q] = 0.0f;
                    }
                }
            }
        }

        // ---- fused 3-pass mainloop: operands loaded once per k-step ----
#pragma unroll
        for (int k = 0; k < 4; k++) {
            const uint32_t kc = (uint32_t)lcolb + (uint32_t)k * 32;
            uint32_t a0h[4], a1h[4], a0l[4], a1l[4];
            ldsm4(a0h[0], a0h[1], a0h[2], a0h[3], abh + arb0 + (kc ^ arx0));
            ldsm4(a1h[0], a1h[1], a1h[2], a1h[3], abh + arb1 + (kc ^ arx1));
            ldsm4(a0l[0], a0l[1], a0l[2], a0l[3], abl + arb0 + (kc ^ arx0));
            ldsm4(a1l[0], a1l[1], a1l[2], a1l[3], abl + arb1 + (kc ^ arx1));
#pragma unroll
            for (int gp = 0; gp < 2; gp++) {
                uint32_t bh[2][4], bl[2][4];
#pragma unroll
                for (int g2 = 0; g2 < 2; g2++) {
                    int g = gp * 2 + g2;
                    ldsm4(bh[g2][0], bh[g2][1], bh[g2][2], bh[g2][3],
                          bbh + brb[g] + (kc ^ brx[g]));
                    ldsm4(bl[g2][0], bl[g2][1], bl[g2][2], bl[g2][3],
                          bbl + brb[g] + (kc ^ brx[g]));
                }
#pragma unroll
                for (int g2 = 0; g2 < 2; g2++) {
                    int g = gp * 2 + g2;
                    mma16816(acc[0][g][0], a0h, bh[g2][0], bh[g2][2]);
                    mma16816(acc[0][g][1], a0h, bh[g2][1], bh[g2][3]);
                    mma16816(acc[1][g][0], a1h, bh[g2][0], bh[g2][2]);
                    mma16816(acc[1][g][1], a1h, bh[g2][1], bh[g2][3]);
                    mma16816(acc[0][g][0], a0l, bh[g2][0], bh[g2][2]);
                    mma16816(acc[0][g][1], a0l, bh[g2][1], bh[g2][3]);
                    mma16816(acc[1][g][0], a1l, bh[g2][0], bh[g2][2]);
                    mma16816(acc[1][g][1], a1l, bh[g2][1], bh[g2][3]);
                    mma16816(acc[0][g][0], a0h, bl[g2][0], bl[g2][2]);
                    mma16816(acc[0][g][1], a0h, bl[g2][1], bl[g2][3]);
                    mma16816(acc[1][g][0], a1h, bl[g2][0], bl[g2][2]);
                    mma16816(acc[1][g][1], a1h, bl[g2][1], bl[g2][3]);
                }
            }
        }

        // release B buffer p (reads done for this warp)
        MBAR_ARRIVE(mb_rd[p]);

        // prefetch B[mq+1] into the other buffer (overlaps other warps' work)
        if (mq < 7) {
            const int np = 1 - p;
            const int mn = mq + 1;
            if (mq >= 1) {
                // wait until all warps finished reading buffer np at iteration mq-1
                MBAR_WAIT_PARITY(mb_rd[np], (uint32_t)((((mq + 1) >> 1) - 1) & 1));
            }
            const uint32_t bufb = smbase + SM_BB + (uint32_t)np * 32768u;
            for (int c = tid; c < 1024; c += 256) {
                int r = c >> 3, ck = c & 7;
                int g = r >> 5, ml = r & 31;
                uint32_t off = swz((uint32_t)r, (uint32_t)ck * 16);
                CP_ASYNC16(bufb + off,
                           __cvta_generic_to_global(&g_wbh[g][s][mn * 32 + ml][ck * 8]));
                CP_ASYNC16(bufb + 16384u + off,
                           __cvta_generic_to_global(&g_wbl[g][s][mn * 32 + ml][ck * 8]));
            }
            CP_ASYNC_MBAR_ARRIVE_NOINC(mb_full[np]);
        }

        // ---- epilogue (all 4 gates live in this thread's registers) ----
        const int mbase = mq * 32 + wc * 16;

        float bia[4][2][2];  // [gate][n-half][cp]
        float c0v[2][2];
#pragma unroll
        for (int h = 0; h < 2; h++) {
#pragma unroll
            for (int cp = 0; cp < 2; cp++) {
                int m = mbase + h * 8 + qcol * 2 + cp;
#pragma unroll
                for (int g = 0; g < 4; g++) {
                    bia[g][h][cp] = bias_s[g * 256 + m];
                }
                c0v[h][cp] = c0_s[m];
            }
        }

#pragma unroll
        for (int mt = 0; mt < 2; mt++) {
#pragma unroll
            for (int rp = 0; rp < 2; rp++) {
                int token = n0 + wr * 32 + mt * 16 + qrow + rp * 8;
#pragma unroll
                for (int h = 0; h < 2; h++) {
                    float hv0, hv1;
#pragma unroll
                    for (int cp = 0; cp < 2; cp++) {
                        int idx = rp * 2 + cp;
                        float iv = sigmoid_f(acc[mt][0][h][idx] + bia[0][h][cp]);
                        float fv = sigmoid_f(acc[mt][1][h][idx] + bia[1][h][cp]);
                        float gv = tanh_f(acc[mt][2][h][idx] + bia[2][h][cp]);
                        float ov = sigmoid_f(acc[mt][3][h][idx] + bia[3][h][cp]);
                        float cc = fv * c0v[h][cp] + iv * gv;
                        float hh = ov * tanh_f(cc);
                        if (cp == 0) { hv0 = hh; } else { hv1 = hh; }
                    }
                    float2 hv;
                    hv.x = hv0;
                    hv.y = hv1;
                    *reinterpret_cast<float2*>(
                        out + (size_t)token * (SS * MM) + s * 256 + mbase + h * 8 + qcol * 2) = hv;
                }
            }
        }
    }
}

// ---------------------------------------------------------------------------
// launch
// ---------------------------------------------------------------------------
extern "C" void kernel_launch(void* const* d_in, const int* in_sizes, int n_in,
                              void* d_out, int out_size) {
    const float* mod = (const float*)d_in[0];
    const float* h0  = (const float*)d_in[1];
    const float* c0  = (const float*)d_in[2];
    const float* Wx  = (const float*)d_in[3];
    const float* bx  = (const float*)d_in[4];
    const float* Wi  = (const float*)d_in[5];
    const float* bi  = (const float*)d_in[6];
    const float* Wf  = (const float*)d_in[7];
    const float* bf  = (const float*)d_in[8];
    const float* Wg  = (const float*)d_in[9];
    const float* bg  = (const float*)d_in[10];
    const float* Wo  = (const float*)d_in[11];
    const float* bo  = (const float*)d_in[12];
    float* out = (float*)d_out;

    cudaFuncSetAttribute(precompute_kernel,
                         cudaFuncAttributeMaxDynamicSharedMemorySize, 98304);
    cudaFuncSetAttribute(lstm_mma_kernel,
                         cudaFuncAttributeMaxDynamicSharedMemorySize, SM_SZ);

    precompute_kernel<<<dim3(SS, 4, 8), 256, 98304>>>(
        Wx, bx, Wi, bi, Wf, bf, Wg, bg, Wo, bo, h0);

    lstm_mma_kernel<<<dim3(NTOK / 128, 1, SS), 256, SM_SZ>>>(mod, c0, out);
}

// round 8
// speedup vs baseline: 3.7573x; 1.1019x over previous
#include <cuda_runtime.h>
#include <cuda_bf16.h>
#include <cstdint>

// Problem constants
#define SS 8        // streams
#define II 64       // modulations per stream
#define MM 256      // features per stream
#define NTOK 16384  // batch

// Fused weights (bf16 hi/lo split): W~_g[s] = Wg[:, :, 0:M] @ Wx[s]  -> [4][S][M][64]
__device__ __nv_bfloat16 g_wbh[4][SS][MM][II];
__device__ __nv_bfloat16 g_wbl[4][SS][MM][II];
// Fused biases:  b~_g[s,m] = bg + Wg_x@bx + Wg_h@h0
__device__ float g_bias[4][SS][MM];

// ---------------------------------------------------------------------------
// helpers
// ---------------------------------------------------------------------------
// hardware tanh (MUFU.TANH, sm_75+): 1 MUFU op, rel err ~2^-11
__device__ __forceinline__ float tanh_f(float x) {
    float y;
    asm("tanh.approx.f32 %0, %1;" : "=f"(y) : "f"(x));
    return y;
}
// sigmoid via hw tanh: sigma(x) = 0.5 + 0.5*tanh(x/2)  (1 MUFU + 2 FMA)
__device__ __forceinline__ float sigmoid_f(float x) {
    float y;
    asm("tanh.approx.f32 %0, %1;" : "=f"(y) : "f"(0.5f * x));
    return fmaf(0.5f, y, 0.5f);
}

// pack two floats into bf16x2 (lo in low half)
__device__ __forceinline__ uint32_t pack_bf16x2(float lo, float hi) {
    uint32_t r;
    asm("cvt.rn.bf16x2.f32 %0, %1, %2;" : "=r"(r) : "f"(hi), "f"(lo));
    return r;
}

__device__ __forceinline__ uint32_t smem_u32(const void* p) {
    uint32_t a;
    asm("{ .reg .u64 t; cvta.to.shared.u64 t, %1; cvt.u32.u64 %0, t; }"
        : "=r"(a) : "l"(p));
    return a;
}

__device__ __forceinline__ void ldsm4(uint32_t& r0, uint32_t& r1,
                                      uint32_t& r2, uint32_t& r3, uint32_t addr) {
    asm volatile("ldmatrix.sync.aligned.m8n8.x4.shared.b16 {%0,%1,%2,%3}, [%4];"
                 : "=r"(r0), "=r"(r1), "=r"(r2), "=r"(r3) : "r"(addr));
}

__device__ __forceinline__ void mma16816(float* c, const uint32_t* a,
                                         uint32_t b0, uint32_t b1) {
    asm volatile(
        "mma.sync.aligned.m16n8k16.row.col.f32.bf16.bf16.f32 "
        "{%0,%1,%2,%3}, {%4,%5,%6,%7}, {%8,%9}, {%0,%1,%2,%3};"
        : "+f"(c[0]), "+f"(c[1]), "+f"(c[2]), "+f"(c[3])
        : "r"(a[0]), "r"(a[1]), "r"(a[2]), "r"(a[3]), "r"(b0), "r"(b1));
}

// swizzled smem byte offset for rows of 128B: XOR 16B-chunk by (row&7)
__device__ __forceinline__ uint32_t swz(uint32_t row, uint32_t colbyte) {
    return row * 128u + (colbyte ^ ((row & 7u) << 4));
}

#define CP_ASYNC16(dst, gsrc) \
    asm volatile("cp.async.cg.shared.global [%0], [%1], 16;" \
                 :: "r"(dst), "l"(gsrc) : "memory")

#define MBAR_INIT(addr, cnt) \
    asm volatile("mbarrier.init.shared.b64 [%0], %1;" :: "r"(addr), "r"(cnt) : "memory")
#define MBAR_ARRIVE(addr) \
    asm volatile("mbarrier.arrive.shared.b64 _, [%0];" :: "r"(addr) : "memory")
#define CP_ASYNC_MBAR_ARRIVE_NOINC(addr) \
    asm volatile("cp.async.mbarrier.arrive.noinc.shared::cta.b64 [%0];" :: "r"(addr) : "memory")

#define MBAR_WAIT_PARITY(addr, par) do {                                        \
    uint32_t _mb = (addr);                                                      \
    uint32_t _pa = (par);                                                       \
    uint32_t _done;                                                             \
    asm volatile(                                                               \
        "{\n\t"                                                                 \
        ".reg .pred p;\n\t"                                                     \
        "mbarrier.try_wait.parity.acquire.cta.shared::cta.b64 p, [%1], %2;\n\t" \
        "selp.b32 %0, 1, 0, p;\n\t"                                             \
        "}" : "=r"(_done) : "r"(_mb), "r"(_pa) : "memory");                     \
    if (!_done) {                                                               \
        asm volatile(                                                           \
            "{\n\t"                                                             \
            ".reg .pred P1;\n\t"                                                \
            "WL_%=:\n\t"                                                        \
            "mbarrier.try_wait.parity.acquire.cta.shared::cta.b64 P1, [%0], %1, 0x989680;\n\t" \
            "@P1 bra.uni WD_%=;\n\t"                                            \
            "bra.uni WL_%=;\n\t"                                                \
            "WD_%=:\n\t"                                                        \
            "}" :: "r"(_mb), "r"(_pa) : "memory");                              \
    }                                                                           \
} while (0)

// ---------------------------------------------------------------------------
// Kernel 1: weight/bias fusion
// grid = (S, 4 gates, 8 m-blocks of 32), block = 256
// smem: wx_s[256*64] (64KB) + wg_s[32*256] (32KB)
// ---------------------------------------------------------------------------
__global__ __launch_bounds__(256, 1)
void precompute_kernel(const float* __restrict__ Wx, const float* __restrict__ bx,
                       const float* __restrict__ Wi, const float* __restrict__ bi,
                       const float* __restrict__ Wf, const float* __restrict__ bf,
                       const float* __restrict__ Wg, const float* __restrict__ bg,
                       const float* __restrict__ Wo, const float* __restrict__ bo,
                       const float* __restrict__ h0) {
    extern __shared__ float smem[];
    float* wx_s = smem;            // [k=256][i=64]
    float* wg_s = smem + 256 * 64; // [mm=32][k=256]

    const int s    = blockIdx.x;
    const int gate = blockIdx.y;
    const int m0   = blockIdx.z * 32;
    const int tid  = threadIdx.x;

    const float* WG;
    const float* bG;
    switch (gate) {
        case 0:  WG = Wi; bG = bi; break;
        case 1:  WG = Wf; bG = bf; break;
        case 2:  WG = Wg; bG = bg; break;
        default: WG = Wo; bG = bo; break;
    }

    for (int idx = tid; idx < 256 * 64; idx += 256) {
        wx_s[idx] = Wx[(size_t)s * 256 * 64 + idx];
    }
    for (int idx = tid; idx < 32 * 256; idx += 256) {
        int mm = idx >> 8, k = idx & 255;
        wg_s[idx] = WG[(size_t)(s * 256 + m0 + mm) * 512 + k];
    }
    __syncthreads();

    const int tx = tid & 63;  // i column
    const int ty = tid >> 6;  // 0..3

    float acc[8];
#pragma unroll
    for (int r = 0; r < 8; r++) {
        acc[r] = 0.0f;
    }

    for (int k = 0; k < 256; k += 4) {
        float x0 = wx_s[(k + 0) * 64 + tx];
        float x1 = wx_s[(k + 1) * 64 + tx];
        float x2 = wx_s[(k + 2) * 64 + tx];
        float x3 = wx_s[(k + 3) * 64 + tx];
#pragma unroll
        for (int r = 0; r < 8; r++) {
            int ml = ty + 4 * r;
            float4 wv = *reinterpret_cast<const float4*>(&wg_s[ml * 256 + k]);
            acc[r] += wv.x * x0;
            acc[r] += wv.y * x1;
            acc[r] += wv.z * x2;
            acc[r] += wv.w * x3;
        }
    }
#pragma unroll
    for (int r = 0; r < 8; r++) {
        int m = m0 + ty + 4 * r;
        float v = acc[r];
        uint32_t p = pack_bf16x2(v, 0.0f);
        float hf = __uint_as_float(p << 16);
        g_wbh[gate][s][m][tx] = __float2bfloat16(v);
        g_wbl[gate][s][m][tx] = __float2bfloat16(v - hf);
    }

    // fused bias: 8 partials of 64 per output row (rows of 32)
    __syncthreads();  // all reads of wx_s done -> reuse as scratch
    {
        const int mm = tid & 31, part = tid >> 5;
        float p = 0.0f;
        if (part < 4) {
            const float* a = wg_s + mm * 256 + part * 64;
            const float* b = bx + s * 256 + part * 64;
#pragma unroll 4
            for (int k = 0; k < 64; k++) {
                p += a[k] * b[k];
            }
        } else {
            const float* a = WG + (size_t)(s * 256 + m0 + mm) * 512 + 256 + (part - 4) * 64;
            const float* b = h0 + s * 256 + (part - 4) * 64;
#pragma unroll 4
            for (int k = 0; k < 64; k++) {
                p += a[k] * b[k];
            }
        }
        wx_s[part * 32 + mm] = p;
        __syncthreads();
        if (tid < 32) {
            float b = bG[s * 256 + m0 + tid];
#pragma unroll
            for (int j = 0; j < 8; j++) {
                b += wx_s[j * 32 + tid];
            }
            g_bias[gate][s][m0 + tid] = b;
        }
    }
}

// ---------------------------------------------------------------------------
// Kernel 2: main LSTM step (mma.sync bf16 split GEMM, persistent over m-octants,
// mbarrier-pipelined B buffers; epilogue uses MUFU.TANH (5 MUFU/output))
// grid = (token-tiles=128, 1, stream=8) = 1024 CTAs, block = 256 (8 warps)
// smem: Ah(16K) Al(16K) + 2 x (Bh(16K)+Bl(16K)) + bias(4K) + c0(1K) + mbarriers
// ---------------------------------------------------------------------------
#define SM_AH   0u
#define SM_AL   16384u
#define SM_BB   32768u     // buffer p at SM_BB + p*32768 (H), +16384 (L)
#define SM_BIAS 98304u     // 1024 floats
#define SM_C0   102400u    // 256 floats
#define SM_MB   103424u    // full0, full1, rd0, rd1 (8B each)
#define SM_SZ   103456u

__global__ __launch_bounds__(256, 2)
void lstm_mma_kernel(const float* __restrict__ mod,
                     const float* __restrict__ c0,
                     float* __restrict__ out) {
    extern __shared__ char sm[];
    char* smp = sm;
    const uint32_t smbase = smem_u32(sm);

    const int s   = blockIdx.z;
    const int n0  = blockIdx.x * 128; // token base
    const int tid = threadIdx.x;

    const uint32_t mb_full[2] = {smbase + SM_MB, smbase + SM_MB + 8};
    const uint32_t mb_rd[2]   = {smbase + SM_MB + 16, smbase + SM_MB + 24};

    if (tid == 0) {
        MBAR_INIT(mb_full[0], 256);
        MBAR_INIT(mb_full[1], 256);
        MBAR_INIT(mb_rd[0], 256);
        MBAR_INIT(mb_rd[1], 256);
    }
    __syncthreads();

    // ---- kick off B[0] via cp.async into buffer 0, tracked by full[0] ----
    for (int c = tid; c < 1024; c += 256) {
        int r = c >> 3, ck = c & 7;
        int g = r >> 5, ml = r & 31;
        uint32_t off = swz((uint32_t)r, (uint32_t)ck * 16);
        CP_ASYNC16(smbase + SM_BB + off,
                   __cvta_generic_to_global(&g_wbh[g][s][ml][ck * 8]));
        CP_ASYNC16(smbase + SM_BB + 16384u + off,
                   __cvta_generic_to_global(&g_wbl[g][s][ml][ck * 8]));
    }
    CP_ASYNC_MBAR_ARRIVE_NOINC(mb_full[0]);

    // ---- stage A (tokens): fp32 -> bf16 hi/lo, SW128 (overlaps B0 copy) ----
    for (int c = tid; c < 1024; c += 256) {
        int row = c >> 3, ck = c & 7;  // 16B chunk = 8 bf16
        const float* src = mod + (size_t)(n0 + row) * (SS * II) + s * II + ck * 8;
        float4 v0 = *reinterpret_cast<const float4*>(src);
        float4 v1 = *reinterpret_cast<const float4*>(src + 4);
        float fv[8];
        fv[0] = v0.x; fv[1] = v0.y; fv[2] = v0.z; fv[3] = v0.w;
        fv[4] = v1.x; fv[5] = v1.y; fv[6] = v1.z; fv[7] = v1.w;
        uint32_t hp[4], lp[4];
#pragma unroll
        for (int j = 0; j < 4; j++) {
            float a = fv[2 * j], b = fv[2 * j + 1];
            uint32_t h = pack_bf16x2(a, b);
            float ha = __uint_as_float(h << 16);
            float hb = __uint_as_float(h & 0xFFFF0000u);
            hp[j] = h;
            lp[j] = pack_bf16x2(a - ha, b - hb);
        }
        uint32_t off = swz((uint32_t)row, (uint32_t)ck * 16);
        *reinterpret_cast<uint4*>(smp + SM_AH + off) = make_uint4(hp[0], hp[1], hp[2], hp[3]);
        *reinterpret_cast<uint4*>(smp + SM_AL + off) = make_uint4(lp[0], lp[1], lp[2], lp[3]);
    }

    // ---- stage biases + c0 into smem ----
    for (int i = tid; i < 1024; i += 256) {
        int g = i >> 8, m = i & 255;
        *reinterpret_cast<float*>(smp + SM_BIAS + i * 4) = g_bias[g][s][m];
    }
    *reinterpret_cast<float*>(smp + SM_C0 + tid * 4) = c0[s * 256 + tid];
    __syncthreads();  // A + bias/c0 visible CTA-wide

    // ---- warp/lane geometry ----
    const int w    = tid >> 5;
    const int lane = tid & 31;
    const int wr   = w >> 1;  // token row group (0..3)
    const int wc   = w & 1;   // m column group (0..1)
    const int lrow  = lane & 15;
    const int lcolb = (lane >> 4) * 16;

    const uint32_t arow0 = (uint32_t)(wr * 32 + lrow);
    const uint32_t arow1 = (uint32_t)(wr * 32 + 16 + lrow);
    const uint32_t arb0 = arow0 * 128, arx0 = (arow0 & 7) << 4;
    const uint32_t arb1 = arow1 * 128, arx1 = (arow1 & 7) << 4;
    uint32_t brb[4], brx[4];
#pragma unroll
    for (int g = 0; g < 4; g++) {
        uint32_t brr = (uint32_t)(g * 32 + wc * 16) + (uint32_t)lrow;
        brb[g] = brr * 128;
        brx[g] = (brr & 7) << 4;
    }
    const uint32_t abh = smbase + SM_AH;
    const uint32_t abl = smbase + SM_AL;

    const int qrow = lane >> 2, qcol = lane & 3;
    const float* bias_s = reinterpret_cast<const float*>(smp + SM_BIAS);
    const float* c0_s   = reinterpret_cast<const float*>(smp + SM_C0);

#pragma unroll 1
    for (int mq = 0; mq < 8; mq++) {
        const int p = mq & 1;
        const uint32_t bbh = smbase + SM_BB + (uint32_t)p * 32768u;
        const uint32_t bbl = bbh + 16384u;

        // wait B[mq] data ready
        MBAR_WAIT_PARITY(mb_full[p], (uint32_t)((mq >> 1) & 1));

        float acc[2][4][2][4];  // [token-tile][gate][n-half][frag]
#pragma unroll
        for (int mt = 0; mt < 2; mt++) {
#pragma unroll
            for (int g = 0; g < 4; g++) {
#pragma unroll
                for (int h = 0; h < 2; h++) {
#pragma unroll
                    for (int q = 0; q < 4; q++) {
                        acc[mt][g][h][q] = 0.0f;
                    }
                }
            }
        }

        // ---- fused 3-pass mainloop: operands loaded once per k-step ----
#pragma unroll
        for (int k = 0; k < 4; k++) {
            const uint32_t kc = (uint32_t)lcolb + (uint32_t)k * 32;
            uint32_t a0h[4], a1h[4], a0l[4], a1l[4];
            ldsm4(a0h[0], a0h[1], a0h[2], a0h[3], abh + arb0 + (kc ^ arx0));
            ldsm4(a1h[0], a1h[1], a1h[2], a1h[3], abh + arb1 + (kc ^ arx1));
            ldsm4(a0l[0], a0l[1], a0l[2], a0l[3], abl + arb0 + (kc ^ arx0));
            ldsm4(a1l[0], a1l[1], a1l[2], a1l[3], abl + arb1 + (kc ^ arx1));
#pragma unroll
            for (int gp = 0; gp < 2; gp++) {
                uint32_t bh[2][4], bl[2][4];
#pragma unroll
                for (int g2 = 0; g2 < 2; g2++) {
                    int g = gp * 2 + g2;
                    ldsm4(bh[g2][0], bh[g2][1], bh[g2][2], bh[g2][3],
                          bbh + brb[g] + (kc ^ brx[g]));
                    ldsm4(bl[g2][0], bl[g2][1], bl[g2][2], bl[g2][3],
                          bbl + brb[g] + (kc ^ brx[g]));
                }
#pragma unroll
                for (int g2 = 0; g2 < 2; g2++) {
                    int g = gp * 2 + g2;
                    mma16816(acc[0][g][0], a0h, bh[g2][0], bh[g2][2]);
                    mma16816(acc[0][g][1], a0h, bh[g2][1], bh[g2][3]);
                    mma16816(acc[1][g][0], a1h, bh[g2][0], bh[g2][2]);
                    mma16816(acc[1][g][1], a1h, bh[g2][1], bh[g2][3]);
                    mma16816(acc[0][g][0], a0l, bh[g2][0], bh[g2][2]);
                    mma16816(acc[0][g][1], a0l, bh[g2][1], bh[g2][3]);
                    mma16816(acc[1][g][0], a1l, bh[g2][0], bh[g2][2]);
                    mma16816(acc[1][g][1], a1l, bh[g2][1], bh[g2][3]);
                    mma16816(acc[0][g][0], a0h, bl[g2][0], bl[g2][2]);
                    mma16816(acc[0][g][1], a0h, bl[g2][1], bl[g2][3]);
                    mma16816(acc[1][g][0], a1h, bl[g2][0], bl[g2][2]);
                    mma16816(acc[1][g][1], a1h, bl[g2][1], bl[g2][3]);
                }
            }
        }

        // release B buffer p (reads done for this warp)
        MBAR_ARRIVE(mb_rd[p]);

        // prefetch B[mq+1] into the other buffer (overlaps other warps' work)
        if (mq < 7) {
            const int np = 1 - p;
            const int mn = mq + 1;
            if (mq >= 1) {
                // wait until all warps finished reading buffer np at iteration mq-1
                MBAR_WAIT_PARITY(mb_rd[np], (uint32_t)((((mq + 1) >> 1) - 1) & 1));
            }
            const uint32_t bufb = smbase + SM_BB + (uint32_t)np * 32768u;
            for (int c = tid; c < 1024; c += 256) {
                int r = c >> 3, ck = c & 7;
                int g = r >> 5, ml = r & 31;
                uint32_t off = swz((uint32_t)r, (uint32_t)ck * 16);
                CP_ASYNC16(bufb + off,
                           __cvta_generic_to_global(&g_wbh[g][s][mn * 32 + ml][ck * 8]));
                CP_ASYNC16(bufb + 16384u + off,
                           __cvta_generic_to_global(&g_wbl[g][s][mn * 32 + ml][ck * 8]));
            }
            CP_ASYNC_MBAR_ARRIVE_NOINC(mb_full[np]);
        }

        // ---- epilogue (all 4 gates live in this thread's registers) ----
        const int mbase = mq * 32 + wc * 16;

        float bia[4][2][2];  // [gate][n-half][cp]
        float c0v[2][2];
#pragma unroll
        for (int h = 0; h < 2; h++) {
#pragma unroll
            for (int cp = 0; cp < 2; cp++) {
                int m = mbase + h * 8 + qcol * 2 + cp;
#pragma unroll
                for (int g = 0; g < 4; g++) {
                    bia[g][h][cp] = bias_s[g * 256 + m];
                }
                c0v[h][cp] = c0_s[m];
            }
        }

#pragma unroll
        for (int mt = 0; mt < 2; mt++) {
#pragma unroll
            for (int rp = 0; rp < 2; rp++) {
                int token = n0 + wr * 32 + mt * 16 + qrow + rp * 8;
#pragma unroll
                for (int h = 0; h < 2; h++) {
                    float hv0, hv1;
#pragma unroll
                    for (int cp = 0; cp < 2; cp++) {
                        int idx = rp * 2 + cp;
                        float iv = sigmoid_f(acc[mt][0][h][idx] + bia[0][h][cp]);
                        float fv = sigmoid_f(acc[mt][1][h][idx] + bia[1][h][cp]);
                        float gv = tanh_f(acc[mt][2][h][idx] + bia[2][h][cp]);
                        float ov = sigmoid_f(acc[mt][3][h][idx] + bia[3][h][cp]);
                        float cc = fv * c0v[h][cp] + iv * gv;
                        float hh = ov * tanh_f(cc);
                        if (cp == 0) { hv0 = hh; } else { hv1 = hh; }
                    }
                    float2 hv;
                    hv.x = hv0;
                    hv.y = hv1;
                    *reinterpret_cast<float2*>(
                        out + (size_t)token * (SS * MM) + s * 256 + mbase + h * 8 + qcol * 2) = hv;
                }
            }
        }
    }
}

// ---------------------------------------------------------------------------
// launch
// ---------------------------------------------------------------------------
extern "C" void kernel_launch(void* const* d_in, const int* in_sizes, int n_in,
                              void* d_out, int out_size) {
    const float* mod = (const float*)d_in[0];
    const float* h0  = (const float*)d_in[1];
    const float* c0  = (const float*)d_in[2];
    const float* Wx  = (const float*)d_in[3];
    const float* bx  = (const float*)d_in[4];
    const float* Wi  = (const float*)d_in[5];
    const float* bi  = (const float*)d_in[6];
    const float* Wf  = (const float*)d_in[7];
    const float* bf  = (const float*)d_in[8];
    const float* Wg  = (const float*)d_in[9];
    const float* bg  = (const float*)d_in[10];
    const float* Wo  = (const float*)d_in[11];
    const float* bo  = (const float*)d_in[12];
    float* out = (float*)d_out;

    cudaFuncSetAttribute(precompute_kernel,
                         cudaFuncAttributeMaxDynamicSharedMemorySize, 98304);
    cudaFuncSetAttribute(lstm_mma_kernel,
                         cudaFuncAttributeMaxDynamicSharedMemorySize, SM_SZ);

    precompute_kernel<<<dim3(SS, 4, 8), 256, 98304>>>(
        Wx, bx, Wi, bi, Wf, bf, Wg, bg, Wo, bo, h0);

    lstm_mma_kernel<<<dim3(NTOK / 128, 1, SS), 256, SM_SZ>>>(mod, c0, out);
}

// round 9
// speedup vs baseline: 4.6816x; 1.2460x over previous
#include <cuda_runtime.h>
#include <cuda_bf16.h>
#include <cuda_fp16.h>
#include <cstdint>

// Problem constants
#define SS 8        // streams
#define II 64       // modulations per stream
#define MM 256      // features per stream
#define NTOK 16384  // batch

// Fused weights (fp16): W~_g[s] = Wg[:, :, 0:M] @ Wx[s]  -> [4][S][M][64]
__device__ __half g_wf16[4][SS][MM][II];
// Fused biases:  b~_g[s,m] = bg + Wg_x@bx + Wg_h@h0
__device__ float g_bias[4][SS][MM];

// ---------------------------------------------------------------------------
// helpers
// ---------------------------------------------------------------------------
// hardware tanh (MUFU.TANH, sm_75+): 1 MUFU op, rel err ~2^-11
__device__ __forceinline__ float tanh_f(float x) {
    float y;
    asm("tanh.approx.f32 %0, %1;" : "=f"(y) : "f"(x));
    return y;
}
// sigmoid via hw tanh: sigma(x) = 0.5 + 0.5*tanh(x/2)  (1 MUFU + 2 FMA)
__device__ __forceinline__ float sigmoid_f(float x) {
    float y;
    asm("tanh.approx.f32 %0, %1;" : "=f"(y) : "f"(0.5f * x));
    return fmaf(0.5f, y, 0.5f);
}

__device__ __forceinline__ uint32_t smem_u32(const void* p) {
    uint32_t a;
    asm("{ .reg .u64 t; cvta.to.shared.u64 t, %1; cvt.u32.u64 %0, t; }"
        : "=r"(a) : "l"(p));
    return a;
}

__device__ __forceinline__ void ldsm4(uint32_t& r0, uint32_t& r1,
                                      uint32_t& r2, uint32_t& r3, uint32_t addr) {
    asm volatile("ldmatrix.sync.aligned.m8n8.x4.shared.b16 {%0,%1,%2,%3}, [%4];"
                 : "=r"(r0), "=r"(r1), "=r"(r2), "=r"(r3) : "r"(addr));
}

__device__ __forceinline__ void mma16816(float* c, const uint32_t* a,
                                         uint32_t b0, uint32_t b1) {
    asm volatile(
        "mma.sync.aligned.m16n8k16.row.col.f32.f16.f16.f32 "
        "{%0,%1,%2,%3}, {%4,%5,%6,%7}, {%8,%9}, {%0,%1,%2,%3};"
        : "+f"(c[0]), "+f"(c[1]), "+f"(c[2]), "+f"(c[3])
        : "r"(a[0]), "r"(a[1]), "r"(a[2]), "r"(a[3]), "r"(b0), "r"(b1));
}

// swizzled smem byte offset for rows of 128B: XOR 16B-chunk by (row&7)
__device__ __forceinline__ uint32_t swz(uint32_t row, uint32_t colbyte) {
    return row * 128u + (colbyte ^ ((row & 7u) << 4));
}

#define CP_ASYNC16(dst, gsrc) \
    asm volatile("cp.async.cg.shared.global [%0], [%1], 16;" \
                 :: "r"(dst), "l"(gsrc) : "memory")

#define MBAR_INIT(addr, cnt) \
    asm volatile("mbarrier.init.shared.b64 [%0], %1;" :: "r"(addr), "r"(cnt) : "memory")
#define MBAR_ARRIVE(addr) \
    asm volatile("mbarrier.arrive.shared.b64 _, [%0];" :: "r"(addr) : "memory")
#define CP_ASYNC_MBAR_ARRIVE_NOINC(addr) \
    asm volatile("cp.async.mbarrier.arrive.noinc.shared::cta.b64 [%0];" :: "r"(addr) : "memory")

#define MBAR_WAIT_PARITY(addr, par) do {                                        \
    uint32_t _mb = (addr);                                                      \
    uint32_t _pa = (par);                                                       \
    uint32_t _done;                                                             \
    asm volatile(                                                               \
        "{\n\t"                                                                 \
        ".reg .pred p;\n\t"                                                     \
        "mbarrier.try_wait.parity.acquire.cta.shared::cta.b64 p, [%1], %2;\n\t" \
        "selp.b32 %0, 1, 0, p;\n\t"                                             \
        "}" : "=r"(_done) : "r"(_mb), "r"(_pa) : "memory");                     \
    if (!_done) {                                                               \
        asm volatile(                                                           \
            "{\n\t"                                                             \
            ".reg .pred P1;\n\t"                                                \
            "WL_%=:\n\t"                                                        \
            "mbarrier.try_wait.parity.acquire.cta.shared::cta.b64 P1, [%0], %1, 0x989680;\n\t" \
            "@P1 bra.uni WD_%=;\n\t"                                            \
            "bra.uni WL_%=;\n\t"                                                \
            "WD_%=:\n\t"                                                        \
            "}" :: "r"(_mb), "r"(_pa) : "memory");                              \
    }                                                                           \
} while (0)

// ---------------------------------------------------------------------------
// Kernel 1: weight/bias fusion
// grid = (S, 4 gates, 8 m-blocks of 32), block = 256
// smem: wx_s[256*64] (64KB) + wg_s[32*256] (32KB)
// ---------------------------------------------------------------------------
__global__ __launch_bounds__(256, 1)
void precompute_kernel(const float* __restrict__ Wx, const float* __restrict__ bx,
                       const float* __restrict__ Wi, const float* __restrict__ bi,
                       const float* __restrict__ Wf, const float* __restrict__ bf,
                       const float* __restrict__ Wg, const float* __restrict__ bg,
                       const float* __restrict__ Wo, const float* __restrict__ bo,
                       const float* __restrict__ h0) {
    extern __shared__ float smem[];
    float* wx_s = smem;            // [k=256][i=64]
    float* wg_s = smem + 256 * 64; // [mm=32][k=256]

    const int s    = blockIdx.x;
    const int gate = blockIdx.y;
    const int m0   = blockIdx.z * 32;
    const int tid  = threadIdx.x;

    const float* WG;
    const float* bG;
    switch (gate) {
        case 0:  WG = Wi; bG = bi; break;
        case 1:  WG = Wf; bG = bf; break;
        case 2:  WG = Wg; bG = bg; break;
        default: WG = Wo; bG = bo; break;
    }

    for (int idx = tid; idx < 256 * 64; idx += 256) {
        wx_s[idx] = Wx[(size_t)s * 256 * 64 + idx];
    }
    for (int idx = tid; idx < 32 * 256; idx += 256) {
        int mm = idx >> 8, k = idx & 255;
        wg_s[idx] = WG[(size_t)(s * 256 + m0 + mm) * 512 + k];
    }
    __syncthreads();

    const int tx = tid & 63;  // i column
    const int ty = tid >> 6;  // 0..3

    float acc[8];
#pragma unroll
    for (int r = 0; r < 8; r++) {
        acc[r] = 0.0f;
    }

    for (int k = 0; k < 256; k += 4) {
        float x0 = wx_s[(k + 0) * 64 + tx];
        float x1 = wx_s[(k + 1) * 64 + tx];
        float x2 = wx_s[(k + 2) * 64 + tx];
        float x3 = wx_s[(k + 3) * 64 + tx];
#pragma unroll
        for (int r = 0; r < 8; r++) {
            int ml = ty + 4 * r;
            float4 wv = *reinterpret_cast<const float4*>(&wg_s[ml * 256 + k]);
            acc[r] += wv.x * x0;
            acc[r] += wv.y * x1;
            acc[r] += wv.z * x2;
            acc[r] += wv.w * x3;
        }
    }
#pragma unroll
    for (int r = 0; r < 8; r++) {
        int m = m0 + ty + 4 * r;
        g_wf16[gate][s][m][tx] = __float2half_rn(acc[r]);
    }

    // fused bias: 8 partials of 64 per output row (rows of 32)
    __syncthreads();  // all reads of wx_s done -> reuse as scratch
    {
        const int mm = tid & 31, part = tid >> 5;
        float p = 0.0f;
        if (part < 4) {
            const float* a = wg_s + mm * 256 + part * 64;
            const float* b = bx + s * 256 + part * 64;
#pragma unroll 4
            for (int k = 0; k < 64; k++) {
                p += a[k] * b[k];
            }
        } else {
            const float* a = WG + (size_t)(s * 256 + m0 + mm) * 512 + 256 + (part - 4) * 64;
            const float* b = h0 + s * 256 + (part - 4) * 64;
#pragma unroll 4
            for (int k = 0; k < 64; k++) {
                p += a[k] * b[k];
            }
        }
        wx_s[part * 32 + mm] = p;
        __syncthreads();
        if (tid < 32) {
            float b = bG[s * 256 + m0 + tid];
#pragma unroll
            for (int j = 0; j < 8; j++) {
                b += wx_s[j * 32 + tid];
            }
            g_bias[gate][s][m0 + tid] = b;
        }
    }
}

// ---------------------------------------------------------------------------
// Kernel 2: main LSTM step (mma.sync fp16 2-pass GEMM: A split hi/lo fp16,
// W plain fp16; persistent over m-octants, mbarrier-pipelined B buffers;
// epilogue uses MUFU.TANH)
// grid = (token-tiles=128, 1, stream=8) = 1024 CTAs, block = 256 (8 warps)
// smem: Ah(16K) Al(16K) + 2 x B(16K) + bias(4K) + c0(1K) + mbarriers ~= 69.3KB
// ---------------------------------------------------------------------------
#define SM_AH   0u
#define SM_AL   16384u
#define SM_BB   32768u     // buffer p at SM_BB + p*16384
#define SM_BIAS 65536u     // 1024 floats
#define SM_C0   69632u     // 256 floats
#define SM_MB   70656u     // full0, full1, rd0, rd1 (8B each)
#define SM_SZ   70688u

__global__ __launch_bounds__(256, 2)
void lstm_mma_kernel(const float* __restrict__ mod,
                     const float* __restrict__ c0,
                     float* __restrict__ out) {
    extern __shared__ char sm[];
    char* smp = sm;
    const uint32_t smbase = smem_u32(sm);

    const int s   = blockIdx.z;
    const int n0  = blockIdx.x * 128; // token base
    const int tid = threadIdx.x;

    const uint32_t mb_full[2] = {smbase + SM_MB, smbase + SM_MB + 8};
    const uint32_t mb_rd[2]   = {smbase + SM_MB + 16, smbase + SM_MB + 24};

    if (tid == 0) {
        MBAR_INIT(mb_full[0], 256);
        MBAR_INIT(mb_full[1], 256);
        MBAR_INIT(mb_rd[0], 256);
        MBAR_INIT(mb_rd[1], 256);
    }
    __syncthreads();

    // ---- kick off B[0] via cp.async into buffer 0, tracked by full[0] ----
    for (int c = tid; c < 1024; c += 256) {
        int r = c >> 3, ck = c & 7;
        int g = r >> 5, ml = r & 31;
        uint32_t off = swz((uint32_t)r, (uint32_t)ck * 16);
        CP_ASYNC16(smbase + SM_BB + off,
                   __cvta_generic_to_global(&g_wf16[g][s][ml][ck * 8]));
    }
    CP_ASYNC_MBAR_ARRIVE_NOINC(mb_full[0]);

    // ---- stage A (tokens): fp32 -> fp16 hi/lo, SW128 (overlaps B0 copy) ----
    for (int c = tid; c < 1024; c += 256) {
        int row = c >> 3, ck = c & 7;  // 16B chunk = 8 fp16
        const float* src = mod + (size_t)(n0 + row) * (SS * II) + s * II + ck * 8;
        float4 v0 = *reinterpret_cast<const float4*>(src);
        float4 v1 = *reinterpret_cast<const float4*>(src + 4);
        float fv[8];
        fv[0] = v0.x; fv[1] = v0.y; fv[2] = v0.z; fv[3] = v0.w;
        fv[4] = v1.x; fv[5] = v1.y; fv[6] = v1.z; fv[7] = v1.w;
        uint32_t hp[4], lp[4];
#pragma unroll
        for (int j = 0; j < 4; j++) {
            float a = fv[2 * j], b = fv[2 * j + 1];
            __half ha = __float2half_rn(a);
            __half hb = __float2half_rn(b);
            float ra = a - __half2float(ha);
            float rb = b - __half2float(hb);
            __half la = __float2half_rn(ra);
            __half lb = __float2half_rn(rb);
            hp[j] = ((uint32_t)__half_as_ushort(hb) << 16) | (uint32_t)__half_as_ushort(ha);
            lp[j] = ((uint32_t)__half_as_ushort(lb) << 16) | (uint32_t)__half_as_ushort(la);
        }
        uint32_t off = swz((uint32_t)row, (uint32_t)ck * 16);
        *reinterpret_cast<uint4*>(smp + SM_AH + off) = make_uint4(hp[0], hp[1], hp[2], hp[3]);
        *reinterpret_cast<uint4*>(smp + SM_AL + off) = make_uint4(lp[0], lp[1], lp[2], lp[3]);
    }

    // ---- stage biases + c0 into smem ----
    for (int i = tid; i < 1024; i += 256) {
        int g = i >> 8, m = i & 255;
        *reinterpret_cast<float*>(smp + SM_BIAS + i * 4) = g_bias[g][s][m];
    }
    *reinterpret_cast<float*>(smp + SM_C0 + tid * 4) = c0[s * 256 + tid];
    __syncthreads();  // A + bias/c0 visible CTA-wide

    // ---- warp/lane geometry ----
    const int w    = tid >> 5;
    const int lane = tid & 31;
    const int wr   = w >> 1;  // token row group (0..3)
    const int wc   = w & 1;   // m column group (0..1)
    const int lrow  = lane & 15;
    const int lcolb = (lane >> 4) * 16;

    const uint32_t arow0 = (uint32_t)(wr * 32 + lrow);
    const uint32_t arow1 = (uint32_t)(wr * 32 + 16 + lrow);
    const uint32_t arb0 = arow0 * 128, arx0 = (arow0 & 7) << 4;
    const uint32_t arb1 = arow1 * 128, arx1 = (arow1 & 7) << 4;
    uint32_t brb[4], brx[4];
#pragma unroll
    for (int g = 0; g < 4; g++) {
        uint32_t brr = (uint32_t)(g * 32 + wc * 16) + (uint32_t)lrow;
        brb[g] = brr * 128;
        brx[g] = (brr & 7) << 4;
    }
    const uint32_t abh = smbase + SM_AH;
    const uint32_t abl = smbase + SM_AL;

    const int qrow = lane >> 2, qcol = lane & 3;
    const float* bias_s = reinterpret_cast<const float*>(smp + SM_BIAS);
    const float* c0_s   = reinterpret_cast<const float*>(smp + SM_C0);

#pragma unroll 1
    for (int mq = 0; mq < 8; mq++) {
        const int p = mq & 1;
        const uint32_t bb = smbase + SM_BB + (uint32_t)p * 16384u;

        // wait B[mq] data ready
        MBAR_WAIT_PARITY(mb_full[p], (uint32_t)((mq >> 1) & 1));

        float acc[2][4][2][4];  // [token-tile][gate][n-half][frag]
#pragma unroll
        for (int mt = 0; mt < 2; mt++) {
#pragma unroll
            for (int g = 0; g < 4; g++) {
#pragma unroll
                for (int h = 0; h < 2; h++) {
#pragma unroll
                    for (int q = 0; q < 4; q++) {
                        acc[mt][g][h][q] = 0.0f;
                    }
                }
            }
        }

        // ---- fused 2-pass mainloop: (Ah + Al) x B, operands loaded once ----
#pragma unroll
        for (int k = 0; k < 4; k++) {
            const uint32_t kc = (uint32_t)lcolb + (uint32_t)k * 32;
            uint32_t a0h[4], a1h[4], a0l[4], a1l[4];
            ldsm4(a0h[0], a0h[1], a0h[2], a0h[3], abh + arb0 + (kc ^ arx0));
            ldsm4(a1h[0], a1h[1], a1h[2], a1h[3], abh + arb1 + (kc ^ arx1));
            ldsm4(a0l[0], a0l[1], a0l[2], a0l[3], abl + arb0 + (kc ^ arx0));
            ldsm4(a1l[0], a1l[1], a1l[2], a1l[3], abl + arb1 + (kc ^ arx1));
#pragma unroll
            for (int gp = 0; gp < 2; gp++) {
                uint32_t bh[2][4];
#pragma unroll
                for (int g2 = 0; g2 < 2; g2++) {
                    int g = gp * 2 + g2;
                    ldsm4(bh[g2][0], bh[g2][1], bh[g2][2], bh[g2][3],
                          bb + brb[g] + (kc ^ brx[g]));
                }
#pragma unroll
                for (int g2 = 0; g2 < 2; g2++) {
                    int g = gp * 2 + g2;
                    mma16816(acc[0][g][0], a0h, bh[g2][0], bh[g2][2]);
                    mma16816(acc[0][g][1], a0h, bh[g2][1], bh[g2][3]);
                    mma16816(acc[1][g][0], a1h, bh[g2][0], bh[g2][2]);
                    mma16816(acc[1][g][1], a1h, bh[g2][1], bh[g2][3]);
                    mma16816(acc[0][g][0], a0l, bh[g2][0], bh[g2][2]);
                    mma16816(acc[0][g][1], a0l, bh[g2][1], bh[g2][3]);
                    mma16816(acc[1][g][0], a1l, bh[g2][0], bh[g2][2]);
                    mma16816(acc[1][g][1], a1l, bh[g2][1], bh[g2][3]);
                }
            }
        }

        // release B buffer p (reads done for this warp)
        MBAR_ARRIVE(mb_rd[p]);

        // prefetch B[mq+1] into the other buffer (overlaps other warps' work)
        if (mq < 7) {
            const int np = 1 - p;
            const int mn = mq + 1;
            if (mq >= 1) {
                // wait until all warps finished reading buffer np at iteration mq-1
                MBAR_WAIT_PARITY(mb_rd[np], (uint32_t)((((mq + 1) >> 1) - 1) & 1));
            }
            const uint32_t bufb = smbase + SM_BB + (uint32_t)np * 16384u;
            for (int c = tid; c < 1024; c += 256) {
                int r = c >> 3, ck = c & 7;
                int g = r >> 5, ml = r & 31;
                uint32_t off = swz((uint32_t)r, (uint32_t)ck * 16);
                CP_ASYNC16(bufb + off,
                           __cvta_generic_to_global(&g_wf16[g][s][mn * 32 + ml][ck * 8]));
            }
            CP_ASYNC_MBAR_ARRIVE_NOINC(mb_full[np]);
        }

        // ---- epilogue (all 4 gates live in this thread's registers) ----
        const int mbase = mq * 32 + wc * 16;

        float bia[4][2][2];  // [gate][n-half][cp]
        float c0v[2][2];
#pragma unroll
        for (int h = 0; h < 2; h++) {
#pragma unroll
            for (int cp = 0; cp < 2; cp++) {
                int m = mbase + h * 8 + qcol * 2 + cp;
#pragma unroll
                for (int g = 0; g < 4; g++) {
                    bia[g][h][cp] = bias_s[g * 256 + m];
                }
                c0v[h][cp] = c0_s[m];
            }
        }

#pragma unroll
        for (int mt = 0; mt < 2; mt++) {
#pragma unroll
            for (int rp = 0; rp < 2; rp++) {
                int token = n0 + wr * 32 + mt * 16 + qrow + rp * 8;
#pragma unroll
                for (int h = 0; h < 2; h++) {
                    float hv0, hv1;
#pragma unroll
                    for (int cp = 0; cp < 2; cp++) {
                        int idx = rp * 2 + cp;
                        float iv = sigmoid_f(acc[mt][0][h][idx] + bia[0][h][cp]);
                        float fv = sigmoid_f(acc[mt][1][h][idx] + bia[1][h][cp]);
                        float gv = tanh_f(acc[mt][2][h][idx] + bia[2][h][cp]);
                        float ov = sigmoid_f(acc[mt][3][h][idx] + bia[3][h][cp]);
                        float cc = fv * c0v[h][cp] + iv * gv;
                        float hh = ov * tanh_f(cc);
                        if (cp == 0) { hv0 = hh; } else { hv1 = hh; }
                    }
                    float2 hv;
                    hv.x = hv0;
                    hv.y = hv1;
                    *reinterpret_cast<float2*>(
                        out + (size_t)token * (SS * MM) + s * 256 + mbase + h * 8 + qcol * 2) = hv;
                }
            }
        }
    }
}

// ---------------------------------------------------------------------------
// launch
// ---------------------------------------------------------------------------
extern "C" void kernel_launch(void* const* d_in, const int* in_sizes, int n_in,
                              void* d_out, int out_size) {
    const float* mod = (const float*)d_in[0];
    const float* h0  = (const float*)d_in[1];
    const float* c0  = (const float*)d_in[2];
    const float* Wx  = (const float*)d_in[3];
    const float* bx  = (const float*)d_in[4];
    const float* Wi  = (const float*)d_in[5];
    const float* bi  = (const float*)d_in[6];
    const float* Wf  = (const float*)d_in[7];
    const float* bf  = (const float*)d_in[8];
    const float* Wg  = (const float*)d_in[9];
    const float* bg  = (const float*)d_in[10];
    const float* Wo  = (const float*)d_in[11];
    const float* bo  = (const float*)d_in[12];
    float* out = (float*)d_out;

    cudaFuncSetAttribute(precompute_kernel,
                         cudaFuncAttributeMaxDynamicSharedMemorySize, 98304);
    cudaFuncSetAttribute(lstm_mma_kernel,
                         cudaFuncAttributeMaxDynamicSharedMemorySize, SM_SZ);

    precompute_kernel<<<dim3(SS, 4, 8), 256, 98304>>>(
        Wx, bx, Wi, bi, Wf, bf, Wg, bg, Wo, bo, h0);

    lstm_mma_kernel<<<dim3(NTOK / 128, 1, SS), 256, SM_SZ>>>(mod, c0, out);
}

// round 10
// speedup vs baseline: 6.2072x; 1.3259x over previous
#include <cuda_runtime.h>
#include <cuda_bf16.h>
#include <cuda_fp16.h>
#include <cstdint>

// Problem constants
#define SS 8        // streams
#define II 64       // modulations per stream
#define MM 256      // features per stream
#define NTOK 16384  // batch

// Fused weights (fp16): W~_g[s] = Wg[:, :, 0:M] @ Wx[s]  -> [4][S][M][64]
__device__ __half g_wf16[4][SS][MM][II];
// Fused biases:  b~_g[s,m] = bg + Wg_x@bx + Wg_h@h0
__device__ float g_bias[4][SS][MM];

// ---------------------------------------------------------------------------
// helpers
// ---------------------------------------------------------------------------
// hardware tanh (MUFU.TANH, sm_75+): 1 MUFU op, rel err ~2^-11
__device__ __forceinline__ float tanh_f(float x) {
    float y;
    asm("tanh.approx.f32 %0, %1;" : "=f"(y) : "f"(x));
    return y;
}
// sigmoid via hw tanh: sigma(x) = 0.5 + 0.5*tanh(x/2)  (1 MUFU + 2 FMA)
__device__ __forceinline__ float sigmoid_f(float x) {
    float y;
    asm("tanh.approx.f32 %0, %1;" : "=f"(y) : "f"(0.5f * x));
    return fmaf(0.5f, y, 0.5f);
}

__device__ __forceinline__ uint32_t smem_u32(const void* p) {
    uint32_t a;
    asm("{ .reg .u64 t; cvta.to.shared.u64 t, %1; cvt.u32.u64 %0, t; }"
        : "=r"(a) : "l"(p));
    return a;
}

__device__ __forceinline__ void ldsm4(uint32_t& r0, uint32_t& r1,
                                      uint32_t& r2, uint32_t& r3, uint32_t addr) {
    asm volatile("ldmatrix.sync.aligned.m8n8.x4.shared.b16 {%0,%1,%2,%3}, [%4];"
                 : "=r"(r0), "=r"(r1), "=r"(r2), "=r"(r3) : "r"(addr));
}

__device__ __forceinline__ void mma16816(float* c, const uint32_t* a,
                                         uint32_t b0, uint32_t b1) {
    asm volatile(
        "mma.sync.aligned.m16n8k16.row.col.f32.f16.f16.f32 "
        "{%0,%1,%2,%3}, {%4,%5,%6,%7}, {%8,%9}, {%0,%1,%2,%3};"
        : "+f"(c[0]), "+f"(c[1]), "+f"(c[2]), "+f"(c[3])
        : "r"(a[0]), "r"(a[1]), "r"(a[2]), "r"(a[3]), "r"(b0), "r"(b1));
}

// swizzled smem byte offset for rows of 128B: XOR 16B-chunk by (row&7)
__device__ __forceinline__ uint32_t swz(uint32_t row, uint32_t colbyte) {
    return row * 128u + (colbyte ^ ((row & 7u) << 4));
}

#define CP_ASYNC16(dst, gsrc) \
    asm volatile("cp.async.cg.shared.global [%0], [%1], 16;" \
                 :: "r"(dst), "l"(gsrc) : "memory")

#define MBAR_INIT(addr, cnt) \
    asm volatile("mbarrier.init.shared.b64 [%0], %1;" :: "r"(addr), "r"(cnt) : "memory")
#define MBAR_ARRIVE(addr) \
    asm volatile("mbarrier.arrive.shared.b64 _, [%0];" :: "r"(addr) : "memory")
#define CP_ASYNC_MBAR_ARRIVE_NOINC(addr) \
    asm volatile("cp.async.mbarrier.arrive.noinc.shared::cta.b64 [%0];" :: "r"(addr) : "memory")

#define MBAR_WAIT_PARITY(addr, par) do {                                        \
    uint32_t _mb = (addr);                                                      \
    uint32_t _pa = (par);                                                       \
    uint32_t _done;                                                             \
    asm volatile(                                                               \
        "{\n\t"                                                                 \
        ".reg .pred p;\n\t"                                                     \
        "mbarrier.try_wait.parity.acquire.cta.shared::cta.b64 p, [%1], %2;\n\t" \
        "selp.b32 %0, 1, 0, p;\n\t"                                             \
        "}" : "=r"(_done) : "r"(_mb), "r"(_pa) : "memory");                     \
    if (!_done) {                                                               \
        asm volatile(                                                           \
            "{\n\t"                                                             \
            ".reg .pred P1;\n\t"                                                \
            "WL_%=:\n\t"                                                        \
            "mbarrier.try_wait.parity.acquire.cta.shared::cta.b64 P1, [%0], %1, 0x989680;\n\t" \
            "@P1 bra.uni WD_%=;\n\t"                                            \
            "bra.uni WL_%=;\n\t"                                                \
            "WD_%=:\n\t"                                                        \
            "}" :: "r"(_mb), "r"(_pa) : "memory");                              \
    }                                                                           \
} while (0)

// ---------------------------------------------------------------------------
// Kernel 1: weight/bias fusion
// grid = (S, 4 gates, 8 m-blocks of 32), block = 256, 2 CTAs/SM
// smem: wx_s[256*64] (64KB) + wg_s[32*256] (32KB)
// ---------------------------------------------------------------------------
__global__ __launch_bounds__(256, 2)
void precompute_kernel(const float* __restrict__ Wx, const float* __restrict__ bx,
                       const float* __restrict__ Wi, const float* __restrict__ bi,
                       const float* __restrict__ Wf, const float* __restrict__ bf,
                       const float* __restrict__ Wg, const float* __restrict__ bg,
                       const float* __restrict__ Wo, const float* __restrict__ bo,
                       const float* __restrict__ h0) {
    extern __shared__ float smem[];
    float* wx_s = smem;            // [k=256][i=64]
    float* wg_s = smem + 256 * 64; // [mm=32][k=256]

    const int s    = blockIdx.x;
    const int gate = blockIdx.y;
    const int m0   = blockIdx.z * 32;
    const int tid  = threadIdx.x;

    const float* WG;
    const float* bG;
    switch (gate) {
        case 0:  WG = Wi; bG = bi; break;
        case 1:  WG = Wf; bG = bf; break;
        case 2:  WG = Wg; bG = bg; break;
        default: WG = Wo; bG = bo; break;
    }

    for (int idx = tid; idx < 256 * 16; idx += 256) {
        reinterpret_cast<float4*>(wx_s)[idx] =
            reinterpret_cast<const float4*>(Wx + (size_t)s * 256 * 64)[idx];
    }
    for (int idx = tid; idx < 32 * 64; idx += 256) {
        int mm = idx >> 6, kq = idx & 63;
        reinterpret_cast<float4*>(wg_s)[mm * 64 + kq] =
            reinterpret_cast<const float4*>(WG + (size_t)(s * 256 + m0 + mm) * 512)[kq];
    }
    __syncthreads();

    const int tx = tid & 63;  // i column
    const int ty = tid >> 6;  // 0..3

    float acc[8];
#pragma unroll
    for (int r = 0; r < 8; r++) {
        acc[r] = 0.0f;
    }

    for (int k = 0; k < 256; k += 4) {
        float x0 = wx_s[(k + 0) * 64 + tx];
        float x1 = wx_s[(k + 1) * 64 + tx];
        float x2 = wx_s[(k + 2) * 64 + tx];
        float x3 = wx_s[(k + 3) * 64 + tx];
#pragma unroll
        for (int r = 0; r < 8; r++) {
            int ml = ty + 4 * r;
            float4 wv = *reinterpret_cast<const float4*>(&wg_s[ml * 256 + k]);
            acc[r] += wv.x * x0;
            acc[r] += wv.y * x1;
            acc[r] += wv.z * x2;
            acc[r] += wv.w * x3;
        }
    }
#pragma unroll
    for (int r = 0; r < 8; r++) {
        int m = m0 + ty + 4 * r;
        g_wf16[gate][s][m][tx] = __float2half_rn(acc[r]);
    }

    // fused bias: 8 partials of 64 per output row (rows of 32), float4 loads
    __syncthreads();  // all reads of wx_s done -> reuse as scratch
    {
        const int mm = tid & 31, part = tid >> 5;
        float p = 0.0f;
        if (part < 4) {
            const float4* a = reinterpret_cast<const float4*>(wg_s + mm * 256 + part * 64);
            const float4* b = reinterpret_cast<const float4*>(bx + s * 256 + part * 64);
#pragma unroll 4
            for (int k = 0; k < 16; k++) {
                float4 av = a[k], bv = b[k];
                p += av.x * bv.x + av.y * bv.y + av.z * bv.z + av.w * bv.w;
            }
        } else {
            const float4* a = reinterpret_cast<const float4*>(
                WG + (size_t)(s * 256 + m0 + mm) * 512 + 256 + (part - 4) * 64);
            const float4* b = reinterpret_cast<const float4*>(h0 + s * 256 + (part - 4) * 64);
#pragma unroll 4
            for (int k = 0; k < 16; k++) {
                float4 av = a[k], bv = b[k];
                p += av.x * bv.x + av.y * bv.y + av.z * bv.z + av.w * bv.w;
            }
        }
        wx_s[part * 32 + mm] = p;
        __syncthreads();
        if (tid < 32) {
            float b = bG[s * 256 + m0 + tid];
#pragma unroll
            for (int j = 0; j < 8; j++) {
                b += wx_s[j * 32 + tid];
            }
            g_bias[gate][s][m0 + tid] = b;
        }
    }
}

// ---------------------------------------------------------------------------
// Kernel 2: main LSTM step (mma.sync fp16 1-pass GEMM; persistent over
// m-octants, mbarrier-pipelined B buffers; epilogue uses MUFU.TANH)
// grid = (token-tiles=128, 1, stream=8) = 1024 CTAs, block = 256 (8 warps)
// smem: A(16K) + 2 x B(16K) + bias(4K) + c0(1K) + mbarriers ~= 53.2KB
// ---------------------------------------------------------------------------
#define SM_AH   0u
#define SM_BB   16384u     // buffer p at SM_BB + p*16384
#define SM_BIAS 49152u     // 1024 floats
#define SM_C0   53248u     // 256 floats
#define SM_MB   54272u     // full0, full1, rd0, rd1 (8B each)
#define SM_SZ   54304u

__global__ __launch_bounds__(256, 2)
void lstm_mma_kernel(const float* __restrict__ mod,
                     const float* __restrict__ c0,
                     float* __restrict__ out) {
    extern __shared__ char sm[];
    char* smp = sm;
    const uint32_t smbase = smem_u32(sm);

    const int s   = blockIdx.z;
    const int n0  = blockIdx.x * 128; // token base
    const int tid = threadIdx.x;

    const uint32_t mb_full[2] = {smbase + SM_MB, smbase + SM_MB + 8};
    const uint32_t mb_rd[2]   = {smbase + SM_MB + 16, smbase + SM_MB + 24};

    if (tid == 0) {
        MBAR_INIT(mb_full[0], 256);
        MBAR_INIT(mb_full[1], 256);
        MBAR_INIT(mb_rd[0], 256);
        MBAR_INIT(mb_rd[1], 256);
    }
    __syncthreads();

    // ---- kick off B[0] via cp.async into buffer 0, tracked by full[0] ----
    for (int c = tid; c < 1024; c += 256) {
        int r = c >> 3, ck = c & 7;
        int g = r >> 5, ml = r & 31;
        uint32_t off = swz((uint32_t)r, (uint32_t)ck * 16);
        CP_ASYNC16(smbase + SM_BB + off,
                   __cvta_generic_to_global(&g_wf16[g][s][ml][ck * 8]));
    }
    CP_ASYNC_MBAR_ARRIVE_NOINC(mb_full[0]);

    // ---- stage A (tokens): fp32 -> fp16, SW128 (overlaps B0 copy) ----
    for (int c = tid; c < 1024; c += 256) {
        int row = c >> 3, ck = c & 7;  // 16B chunk = 8 fp16
        const float* src = mod + (size_t)(n0 + row) * (SS * II) + s * II + ck * 8;
        float4 v0 = *reinterpret_cast<const float4*>(src);
        float4 v1 = *reinterpret_cast<const float4*>(src + 4);
        float fv[8];
        fv[0] = v0.x; fv[1] = v0.y; fv[2] = v0.z; fv[3] = v0.w;
        fv[4] = v1.x; fv[5] = v1.y; fv[6] = v1.z; fv[7] = v1.w;
        uint32_t hp[4];
#pragma unroll
        for (int j = 0; j < 4; j++) {
            __half ha = __float2half_rn(fv[2 * j]);
            __half hb = __float2half_rn(fv[2 * j + 1]);
            hp[j] = ((uint32_t)__half_as_ushort(hb) << 16) | (uint32_t)__half_as_ushort(ha);
        }
        uint32_t off = swz((uint32_t)row, (uint32_t)ck * 16);
        *reinterpret_cast<uint4*>(smp + SM_AH + off) = make_uint4(hp[0], hp[1], hp[2], hp[3]);
    }

    // ---- stage biases + c0 into smem ----
    for (int i = tid; i < 1024; i += 256) {
        int g = i >> 8, m = i & 255;
        *reinterpret_cast<float*>(smp + SM_BIAS + i * 4) = g_bias[g][s][m];
    }
    *reinterpret_cast<float*>(smp + SM_C0 + tid * 4) = c0[s * 256 + tid];
    __syncthreads();  // A + bias/c0 visible CTA-wide

    // ---- warp/lane geometry ----
    const int w    = tid >> 5;
    const int lane = tid & 31;
    const int wr   = w >> 1;  // token row group (0..3)
    const int wc   = w & 1;   // m column group (0..1)
    const int lrow  = lane & 15;
    const int lcolb = (lane >> 4) * 16;

    const uint32_t arow0 = (uint32_t)(wr * 32 + lrow);
    const uint32_t arow1 = (uint32_t)(wr * 32 + 16 + lrow);
    const uint32_t arb0 = arow0 * 128, arx0 = (arow0 & 7) << 4;
    const uint32_t arb1 = arow1 * 128, arx1 = (arow1 & 7) << 4;
    uint32_t brb[4], brx[4];
#pragma unroll
    for (int g = 0; g < 4; g++) {
        uint32_t brr = (uint32_t)(g * 32 + wc * 16) + (uint32_t)lrow;
        brb[g] = brr * 128;
        brx[g] = (brr & 7) << 4;
    }
    const uint32_t abh = smbase + SM_AH;

    const int qrow = lane >> 2, qcol = lane & 3;
    const float* bias_s = reinterpret_cast<const float*>(smp + SM_BIAS);
    const float* c0_s   = reinterpret_cast<const float*>(smp + SM_C0);

#pragma unroll 1
    for (int mq = 0; mq < 8; mq++) {
        const int p = mq & 1;
        const uint32_t bb = smbase + SM_BB + (uint32_t)p * 16384u;

        // wait B[mq] data ready
        MBAR_WAIT_PARITY(mb_full[p], (uint32_t)((mq >> 1) & 1));

        float acc[2][4][2][4];  // [token-tile][gate][n-half][frag]
#pragma unroll
        for (int mt = 0; mt < 2; mt++) {
#pragma unroll
            for (int g = 0; g < 4; g++) {
#pragma unroll
                for (int h = 0; h < 2; h++) {
#pragma unroll
                    for (int q = 0; q < 4; q++) {
                        acc[mt][g][h][q] = 0.0f;
                    }
                }
            }
        }

        // ---- 1-pass fp16 mainloop ----
#pragma unroll
        for (int k = 0; k < 4; k++) {
            const uint32_t kc = (uint32_t)lcolb + (uint32_t)k * 32;
            uint32_t a0[4], a1[4];
            ldsm4(a0[0], a0[1], a0[2], a0[3], abh + arb0 + (kc ^ arx0));
            ldsm4(a1[0], a1[1], a1[2], a1[3], abh + arb1 + (kc ^ arx1));
#pragma unroll
            for (int gp = 0; gp < 2; gp++) {
                uint32_t bh[2][4];
#pragma unroll
                for (int g2 = 0; g2 < 2; g2++) {
                    int g = gp * 2 + g2;
                    ldsm4(bh[g2][0], bh[g2][1], bh[g2][2], bh[g2][3],
                          bb + brb[g] + (kc ^ brx[g]));
                }
#pragma unroll
                for (int g2 = 0; g2 < 2; g2++) {
                    int g = gp * 2 + g2;
                    mma16816(acc[0][g][0], a0, bh[g2][0], bh[g2][2]);
                    mma16816(acc[0][g][1], a0, bh[g2][1], bh[g2][3]);
                    mma16816(acc[1][g][0], a1, bh[g2][0], bh[g2][2]);
                    mma16816(acc[1][g][1], a1, bh[g2][1], bh[g2][3]);
                }
            }
        }

        // release B buffer p (reads done for this warp)
        MBAR_ARRIVE(mb_rd[p]);

        // prefetch B[mq+1] into the other buffer (overlaps other warps' work)
        if (mq < 7) {
            const int np = 1 - p;
            const int mn = mq + 1;
            if (mq >= 1) {
                // wait until all warps finished reading buffer np at iteration mq-1
                MBAR_WAIT_PARITY(mb_rd[np], (uint32_t)((((mq + 1) >> 1) - 1) & 1));
            }
            const uint32_t bufb = smbase + SM_BB + (uint32_t)np * 16384u;
            for (int c = tid; c < 1024; c += 256) {
                int r = c >> 3, ck = c & 7;
                int g = r >> 5, ml = r & 31;
                uint32_t off = swz((uint32_t)r, (uint32_t)ck * 16);
                CP_ASYNC16(bufb + off,
                           __cvta_generic_to_global(&g_wf16[g][s][mn * 32 + ml][ck * 8]));
            }
            CP_ASYNC_MBAR_ARRIVE_NOINC(mb_full[np]);
        }

        // ---- epilogue (all 4 gates live in this thread's registers) ----
        const int mbase = mq * 32 + wc * 16;

        float bia[4][2][2];  // [gate][n-half][cp]
        float c0v[2][2];
#pragma unroll
        for (int h = 0; h < 2; h++) {
#pragma unroll
            for (int cp = 0; cp < 2; cp++) {
                int m = mbase + h * 8 + qcol * 2 + cp;
#pragma unroll
                for (int g = 0; g < 4; g++) {
                    bia[g][h][cp] = bias_s[g * 256 + m];
                }
                c0v[h][cp] = c0_s[m];
            }
        }

#pragma unroll
        for (int mt = 0; mt < 2; mt++) {
#pragma unroll
            for (int rp = 0; rp < 2; rp++) {
                int token = n0 + wr * 32 + mt * 16 + qrow + rp * 8;
#pragma unroll
                for (int h = 0; h < 2; h++) {
                    float hv0, hv1;
#pragma unroll
                    for (int cp = 0; cp < 2; cp++) {
                        int idx = rp * 2 + cp;
                        float iv = sigmoid_f(acc[mt][0][h][idx] + bia[0][h][cp]);
                        float fv = sigmoid_f(acc[mt][1][h][idx] + bia[1][h][cp]);
                        float gv = tanh_f(acc[mt][2][h][idx] + bia[2][h][cp]);
                        float ov = sigmoid_f(acc[mt][3][h][idx] + bia[3][h][cp]);
                        float cc = fv * c0v[h][cp] + iv * gv;
                        float hh = ov * tanh_f(cc);
                        if (cp == 0) { hv0 = hh; } else { hv1 = hh; }
                    }
                    float2 hv;
                    hv.x = hv0;
                    hv.y = hv1;
                    *reinterpret_cast<float2*>(
                        out + (size_t)token * (SS * MM) + s * 256 + mbase + h * 8 + qcol * 2) = hv;
                }
            }
        }
    }
}

// ---------------------------------------------------------------------------
// launch
// ---------------------------------------------------------------------------
extern "C" void kernel_launch(void* const* d_in, const int* in_sizes, int n_in,
                              void* d_out, int out_size) {
    const float* mod = (const float*)d_in[0];
    const float* h0  = (const float*)d_in[1];
    const float* c0  = (const float*)d_in[2];
    const float* Wx  = (const float*)d_in[3];
    const float* bx  = (const float*)d_in[4];
    const float* Wi  = (const float*)d_in[5];
    const float* bi  = (const float*)d_in[6];
    const float* Wf  = (const float*)d_in[7];
    const float* bf  = (const float*)d_in[8];
    const float* Wg  = (const float*)d_in[9];
    const float* bg  = (const float*)d_in[10];
    const float* Wo  = (const float*)d_in[11];
    const float* bo  = (const float*)d_in[12];
    float* out = (float*)d_out;

    cudaFuncSetAttribute(precompute_kernel,
                         cudaFuncAttributeMaxDynamicSharedMemorySize, 98304);
    cudaFuncSetAttribute(lstm_mma_kernel,
                         cudaFuncAttributeMaxDynamicSharedMemorySize, SM_SZ);

    precompute_kernel<<<dim3(SS, 4, 8), 256, 98304>>>(
        Wx, bx, Wi, bi, Wf, bf, Wg, bg, Wo, bo, h0);

    lstm_mma_kernel<<<dim3(NTOK / 128, 1, SS), 256, SM_SZ>>>(mod, c0, out);
}